// round 3
// baseline (speedup 1.0000x reference)
#include <cuda_runtime.h>
#include <cstdint>

#define NODES_MAX 100000
#define C_IN  64
#define C_HID 128

// Scratch (static __device__ arrays — allocation-free per harness rules)
__device__ float g_deg [NODES_MAX];
__device__ float g_agg1[(size_t)NODES_MAX * C_IN];
__device__ float g_h   [(size_t)NODES_MAX * C_HID];
__device__ float g_agg2[(size_t)NODES_MAX * C_HID];

__device__ __forceinline__ void red_add_v4(float* addr, float4 v) {
    asm volatile("red.global.add.v4.f32 [%0], {%1,%2,%3,%4};"
                 :: "l"(addr), "f"(v.x), "f"(v.y), "f"(v.z), "f"(v.w)
                 : "memory");
}

__device__ __forceinline__ void red_add_f32(float* addr, float v) {
    asm volatile("red.global.add.f32 [%0], %1;"
                 :: "l"(addr), "f"(v) : "memory");
}

// One thread per (edge, float4-group). Gather from src row, vector-reduce into dst row.
// DO_DEG: lane handling group 0 also bumps the degree counter (layer 1 only).
template<int C4, bool DO_DEG>
__global__ void scatter_kernel(const float* __restrict__ x,
                               const int*   __restrict__ src,
                               const int*   __restrict__ dst,
                               float*       __restrict__ agg,
                               float*       __restrict__ deg,
                               int E) {
    int idx = blockIdx.x * blockDim.x + threadIdx.x;
    int total = E * C4;
    if (idx >= total) return;
    int e = idx / C4;          // power-of-two C4 -> shift
    int q = idx - e * C4;
    int s = __ldg(&src[e]);
    int d = __ldg(&dst[e]);
    float4 v = *(const float4*)(x + ((size_t)s * C4 + q) * 4);
    red_add_v4(agg + ((size_t)d * C4 + q) * 4, v);
    if (DO_DEG && q == 0) red_add_f32(deg + d, 1.0f);
}

// out[node][c] = act( (agg[node]/max(deg,1)) @ Wl^T + bias + xin[node] @ Wr^T )
// blockDim = OUTC (one thread per output channel), T nodes per block.
// Weights staged in smem [c][k] with stride INC+4 (16B-aligned, conflict-free LDS.128).
// Node rows in smem [t][k]; reads are warp-broadcast.
// ACT: 0 = relu, 1 = sigmoid.
template<int INC, int OUTC, int T, int ACT>
__global__ void gemm_kernel(const float* __restrict__ agg,
                            const float* __restrict__ xin,
                            const float* __restrict__ deg,
                            const float* __restrict__ Wl,
                            const float* __restrict__ Wr,
                            const float* __restrict__ bias,
                            float*       __restrict__ out,
                            int n) {
    constexpr int WS = INC + 4;
    __shared__ float w_s[OUTC * WS];
    __shared__ float v_s[T * INC];

    const int tid   = threadIdx.x;   // output channel
    const int node0 = blockIdx.x * T;

    float acc[T];
    float b = bias[tid];
    #pragma unroll
    for (int t = 0; t < T; t++) acc[t] = b;

    // ---- Phase A: aggregate part (agg / deg) @ Wl^T ----
    for (int i = tid; i < OUTC * INC; i += OUTC) {
        int c = i / INC, k = i - c * INC;
        w_s[c * WS + k] = Wl[i];
    }
    for (int i = tid; i < T * INC; i += OUTC) {
        int nl = i / INC, k = i - nl * INC;
        int node = node0 + nl;
        float val = 0.f;
        if (node < n) {
            float dg = __ldg(&deg[node]);
            val = agg[(size_t)node * INC + k] * (1.0f / fmaxf(dg, 1.0f));
        }
        v_s[i] = val;
    }
    __syncthreads();

    for (int kk = 0; kk < INC; kk += 4) {
        float4 w = *(const float4*)&w_s[tid * WS + kk];
        #pragma unroll
        for (int t = 0; t < T; t++) {
            float4 v = *(const float4*)&v_s[t * INC + kk];
            acc[t] += w.x * v.x + w.y * v.y + w.z * v.z + w.w * v.w;
        }
    }
    __syncthreads();

    // ---- Phase B: self part xin @ Wr^T ----
    for (int i = tid; i < OUTC * INC; i += OUTC) {
        int c = i / INC, k = i - c * INC;
        w_s[c * WS + k] = Wr[i];
    }
    for (int i = tid; i < T * INC; i += OUTC) {
        int nl = i / INC;
        int node = node0 + nl;
        v_s[i] = (node < n) ? xin[(size_t)node * INC + (i - nl * INC)] : 0.f;
    }
    __syncthreads();

    for (int kk = 0; kk < INC; kk += 4) {
        float4 w = *(const float4*)&w_s[tid * WS + kk];
        #pragma unroll
        for (int t = 0; t < T; t++) {
            float4 v = *(const float4*)&v_s[t * INC + kk];
            acc[t] += w.x * v.x + w.y * v.y + w.z * v.z + w.w * v.w;
        }
    }

    // ---- Epilogue ----
    #pragma unroll
    for (int t = 0; t < T; t++) {
        int node = node0 + t;
        if (node < n) {
            float v = acc[t];
            if (ACT == 0) v = fmaxf(v, 0.f);
            else          v = 1.0f / (1.0f + __expf(-v));
            out[(size_t)node * OUTC + tid] = v;
        }
    }
}

extern "C" void kernel_launch(void* const* d_in, const int* in_sizes, int n_in,
                              void* d_out, int out_size) {
    const float* x   = (const float*)d_in[0];
    const int*   ei  = (const int*)  d_in[1];
    const float* W1l = (const float*)d_in[2];
    const float* W1r = (const float*)d_in[3];
    const float* b1  = (const float*)d_in[4];
    const float* W2l = (const float*)d_in[5];
    const float* W2r = (const float*)d_in[6];
    const float* b2  = (const float*)d_in[7];
    float* out = (float*)d_out;

    const int n = in_sizes[0] / C_IN;
    const int E = in_sizes[1] / 2;
    const int* src = ei;
    const int* dst = ei + E;

    float *deg, *agg1, *h, *agg2;
    cudaGetSymbolAddress((void**)&deg,  g_deg);
    cudaGetSymbolAddress((void**)&agg1, g_agg1);
    cudaGetSymbolAddress((void**)&h,    g_h);
    cudaGetSymbolAddress((void**)&agg2, g_agg2);

    cudaMemsetAsync(deg,  0, (size_t)n * sizeof(float));
    cudaMemsetAsync(agg1, 0, (size_t)n * C_IN  * sizeof(float));
    cudaMemsetAsync(agg2, 0, (size_t)n * C_HID * sizeof(float));

    // Layer 1 scatter (+degree)
    {
        int total = E * (C_IN / 4);
        scatter_kernel<C_IN / 4, true><<<(total + 255) / 256, 256>>>(
            x, src, dst, agg1, deg, E);
    }
    // Layer 1 dense: h = relu(agg1/deg @ W1_l^T + b1 + x @ W1_r^T)
    gemm_kernel<C_IN, C_HID, 16, 0><<<(n + 15) / 16, C_HID>>>(
        agg1, x, deg, W1l, W1r, b1, h, n);

    // Layer 2 scatter
    {
        int total = E * (C_HID / 4);
        scatter_kernel<C_HID / 4, false><<<(total + 255) / 256, 256>>>(
            h, src, dst, agg2, nullptr, E);
    }
    // Layer 2 dense: out = sigmoid(agg2/deg @ W2_l^T + b2 + h @ W2_r^T)
    gemm_kernel<C_HID, C_IN, 16, 1><<<(n + 15) / 16, C_IN>>>(
        agg2, h, deg, W2l, W2r, b2, out, n);
}

// round 4
// speedup vs baseline: 2.0869x; 2.0869x over previous
#include <cuda_runtime.h>
#include <cstdint>

#define NODES_MAX 100000
#define C_IN  64
#define C_HID 128

// Scratch (static __device__ arrays — allocation-free per harness rules)
__device__ float g_deg [NODES_MAX];                       // degree -> 1/max(deg,1)
__device__ float g_agg1[(size_t)NODES_MAX * C_IN];        // layer-1 scatter accumulator
__device__ float g_h   [(size_t)NODES_MAX * C_HID];       // layer-1 output
__device__ float g_ps  [(size_t)NODES_MAX * C_HID];       // [P | S] for layer 2
__device__ float g_agg2[(size_t)NODES_MAX * C_IN];        // layer-2 scatter accumulator (on P, 64-wide)
__device__ float g_wt1 [C_HID * C_HID];                   // packed W1 cat, transposed [k][c]
__device__ float g_wt2 [C_HID * C_HID];                   // packed W2 cat, transposed [k][c]

__device__ __forceinline__ void red_add_v4(float* addr, float4 v) {
    asm volatile("red.global.add.v4.f32 [%0], {%1,%2,%3,%4};"
                 :: "l"(addr), "f"(v.x), "f"(v.y), "f"(v.z), "f"(v.w)
                 : "memory");
}
__device__ __forceinline__ void red_add_f32(float* addr, float v) {
    asm volatile("red.global.add.f32 [%0], %1;"
                 :: "l"(addr), "f"(v) : "memory");
}

// ---------------------------------------------------------------------------
// Weight packing (runs once per launch, trivial cost).
// Wt1[k*128+c] : layer1 cat-K weights, k<64 -> W1l[c][k], else W1r[c][k-64]
// Wt2[k*128+c] : layer2 cat-C weights, c<64 -> W2l[c][k], else W2r[c-64][k]
// ---------------------------------------------------------------------------
__global__ void pack_weights(const float* __restrict__ W1l, const float* __restrict__ W1r,
                             const float* __restrict__ W2l, const float* __restrict__ W2r,
                             float* __restrict__ Wt1, float* __restrict__ Wt2) {
    int i = blockIdx.x * blockDim.x + threadIdx.x;
    if (i >= 128 * 128) return;
    int k = i >> 7, c = i & 127;
    Wt1[i] = (k < 64) ? W1l[c * 64 + k] : W1r[c * 64 + (k - 64)];
    Wt2[i] = (c < 64) ? W2l[c * 128 + k] : W2r[(c - 64) * 128 + k];
}

__global__ void invdeg_kernel(float* __restrict__ deg, int n) {
    int i = blockIdx.x * blockDim.x + threadIdx.x;
    if (i < n) deg[i] = 1.0f / fmaxf(deg[i], 1.0f);
}

// ---------------------------------------------------------------------------
// Scatter: one thread per (edge, float4 group). 16 groups -> 64-wide rows.
// LD = source row stride in floats (64 for x, 128 for PS where P is cols 0..63).
// ---------------------------------------------------------------------------
template<bool DO_DEG>
__global__ void scatter_kernel(const float* __restrict__ x, int ld,
                               const int*   __restrict__ src,
                               const int*   __restrict__ dst,
                               float*       __restrict__ agg,
                               float*       __restrict__ deg,
                               int E) {
    int idx = blockIdx.x * blockDim.x + threadIdx.x;
    if (idx >= E * 16) return;
    int e = idx >> 4;
    int q = idx & 15;
    int s = __ldg(&src[e]);
    int d = __ldg(&dst[e]);
    float4 v = *(const float4*)(x + (size_t)s * ld + q * 4);
    red_add_v4(agg + ((size_t)d * 16 + q) * 4, v);
    if (DO_DEG && q == 0) red_add_f32(deg + d, 1.0f);
}

// ---------------------------------------------------------------------------
// Register-tiled GEMM: out[M x 128] = A_cat[M x 128] @ Wt (K=128).
// Block: 256 threads, tile 128 nodes x 128 channels, thread = 8x8 accumulator.
// MODE 0 (layer 1): A_cat[m][k] = k<64 ? Aa[m][k]*invd[m] : Ab[m][k-64]; +bias, relu
// MODE 1 (layer 2): A_cat[m][k] = Aa[m][k] (Aa width 128); raw store
// Wt is pre-transposed [k][c] -> conflict-free vector fills & frag loads.
// ---------------------------------------------------------------------------
template<int MODE>
__global__ __launch_bounds__(256, 2)
void gemm_tile(const float* __restrict__ Aa,
               const float* __restrict__ Ab,
               const float* __restrict__ invd,
               const float* __restrict__ Wt,
               const float* __restrict__ bias,
               float*       __restrict__ out,
               int n) {
    __shared__ float A_s[128 * 17];   // [m_local][k] stride 17: a-frag reads broadcast, banks 0/8
    __shared__ float W_s[16 * 128];   // [k][c]: w-frag LDS.128 coalesced

    const int tid = threadIdx.x;
    const int tx  = tid & 15;         // channel group (8 channels)
    const int ty  = tid >> 4;         // node group   (8 nodes)
    const int node0 = blockIdx.x * 128;

    float acc[8][8];
    if (MODE == 0) {
        float4 b0 = *(const float4*)(bias + tx * 8);
        float4 b1 = *(const float4*)(bias + tx * 8 + 4);
        #pragma unroll
        for (int i = 0; i < 8; i++) {
            acc[i][0] = b0.x; acc[i][1] = b0.y; acc[i][2] = b0.z; acc[i][3] = b0.w;
            acc[i][4] = b1.x; acc[i][5] = b1.y; acc[i][6] = b1.z; acc[i][7] = b1.w;
        }
    } else {
        #pragma unroll
        for (int i = 0; i < 8; i++)
            #pragma unroll
            for (int j = 0; j < 8; j++) acc[i][j] = 0.f;
    }

    for (int kc = 0; kc < 8; kc++) {
        __syncthreads();   // protect previous iteration's reads

        // W chunk: 16x128 floats = 512 float4, 2 per thread, fully coalesced
        {
            const float4* wg = (const float4*)(Wt + kc * 16 * 128);
            float4* ws = (float4*)W_s;
            ws[tid]       = wg[tid];
            ws[tid + 256] = wg[tid + 256];
        }
        // A chunk: 128 rows x 16 cols = 512 float4 reads, scalar smem stores
        #pragma unroll
        for (int r = 0; r < 2; r++) {
            int idx = tid + r * 256;          // 0..511
            int m_l = idx >> 2;
            int kq  = idx & 3;
            int m   = node0 + m_l;
            int g   = kc * 16 + kq * 4;       // global K column
            float4 v = make_float4(0.f, 0.f, 0.f, 0.f);
            if (m < n) {
                if (MODE == 0) {
                    if (g < 64) {
                        v = *(const float4*)(Aa + (size_t)m * 64 + g);
                        float s = __ldg(&invd[m]);
                        v.x *= s; v.y *= s; v.z *= s; v.w *= s;
                    } else {
                        v = *(const float4*)(Ab + (size_t)m * 64 + (g - 64));
                    }
                } else {
                    v = *(const float4*)(Aa + (size_t)m * 128 + g);
                }
            }
            float* as = &A_s[m_l * 17 + kq * 4];
            as[0] = v.x; as[1] = v.y; as[2] = v.z; as[3] = v.w;
        }
        __syncthreads();

        #pragma unroll
        for (int k = 0; k < 16; k++) {
            float a[8];
            #pragma unroll
            for (int i = 0; i < 8; i++) a[i] = A_s[(ty * 8 + i) * 17 + k];
            float4 w0 = *(const float4*)&W_s[k * 128 + tx * 8];
            float4 w1 = *(const float4*)&W_s[k * 128 + tx * 8 + 4];
            float w[8] = {w0.x, w0.y, w0.z, w0.w, w1.x, w1.y, w1.z, w1.w};
            #pragma unroll
            for (int i = 0; i < 8; i++)
                #pragma unroll
                for (int j = 0; j < 8; j++)
                    acc[i][j] = fmaf(a[i], w[j], acc[i][j]);
        }
    }

    // Epilogue
    #pragma unroll
    for (int i = 0; i < 8; i++) {
        int m = node0 + ty * 8 + i;
        if (m < n) {
            if (MODE == 0) {
                #pragma unroll
                for (int j = 0; j < 8; j++) acc[i][j] = fmaxf(acc[i][j], 0.f);
            }
            float* op = out + (size_t)m * 128 + tx * 8;
            *(float4*)(op)     = make_float4(acc[i][0], acc[i][1], acc[i][2], acc[i][3]);
            *(float4*)(op + 4) = make_float4(acc[i][4], acc[i][5], acc[i][6], acc[i][7]);
        }
    }
}

// out[m][c] = sigmoid(agg2[m][c]*invd[m] + S[m][c] + b2[c]),  S = PS[:,64:128]
__global__ void final_kernel(const float* __restrict__ agg2,
                             const float* __restrict__ ps,
                             const float* __restrict__ invd,
                             const float* __restrict__ b2,
                             float* __restrict__ out, int n) {
    int idx = blockIdx.x * blockDim.x + threadIdx.x;
    if (idx >= n * 16) return;
    int m = idx >> 4;
    int q = (idx & 15) * 4;
    float iv = __ldg(&invd[m]);
    float4 a = *(const float4*)(agg2 + (size_t)m * 64 + q);
    float4 s = *(const float4*)(ps + (size_t)m * 128 + 64 + q);
    float4 b = *(const float4*)(b2 + q);
    float4 r;
    r.x = 1.0f / (1.0f + __expf(-(a.x * iv + s.x + b.x)));
    r.y = 1.0f / (1.0f + __expf(-(a.y * iv + s.y + b.y)));
    r.z = 1.0f / (1.0f + __expf(-(a.z * iv + s.z + b.z)));
    r.w = 1.0f / (1.0f + __expf(-(a.w * iv + s.w + b.w)));
    *(float4*)(out + (size_t)m * 64 + q) = r;
}

extern "C" void kernel_launch(void* const* d_in, const int* in_sizes, int n_in,
                              void* d_out, int out_size) {
    const float* x   = (const float*)d_in[0];
    const int*   ei  = (const int*)  d_in[1];
    const float* W1l = (const float*)d_in[2];
    const float* W1r = (const float*)d_in[3];
    const float* b1  = (const float*)d_in[4];
    const float* W2l = (const float*)d_in[5];
    const float* W2r = (const float*)d_in[6];
    const float* b2  = (const float*)d_in[7];
    float* out = (float*)d_out;

    const int n = in_sizes[0] / C_IN;
    const int E = in_sizes[1] / 2;
    const int* src = ei;
    const int* dst = ei + E;

    float *deg, *agg1, *h, *ps, *agg2, *wt1, *wt2;
    cudaGetSymbolAddress((void**)&deg,  g_deg);
    cudaGetSymbolAddress((void**)&agg1, g_agg1);
    cudaGetSymbolAddress((void**)&h,    g_h);
    cudaGetSymbolAddress((void**)&ps,   g_ps);
    cudaGetSymbolAddress((void**)&agg2, g_agg2);
    cudaGetSymbolAddress((void**)&wt1,  g_wt1);
    cudaGetSymbolAddress((void**)&wt2,  g_wt2);

    cudaMemsetAsync(deg,  0, (size_t)n * sizeof(float));
    cudaMemsetAsync(agg1, 0, (size_t)n * C_IN * sizeof(float));
    cudaMemsetAsync(agg2, 0, (size_t)n * C_IN * sizeof(float));

    pack_weights<<<64, 256>>>(W1l, W1r, W2l, W2r, wt1, wt2);

    // Layer-1 scatter (+degree), x is 64-wide
    {
        int total = E * 16;
        scatter_kernel<true><<<(total + 255) / 256, 256>>>(x, C_IN, src, dst, agg1, deg, E);
    }
    invdeg_kernel<<<(n + 255) / 256, 256>>>(deg, n);

    // Layer 1: h = relu([agg1*invd | x] @ Wt1 + b1)
    gemm_tile<0><<<(n + 127) / 128, 256>>>(agg1, x, deg, wt1, b1, h, n);

    // Layer 2 dense first (linearity of mean): PS = h @ [W2l ; W2r]^T  -> [P | S]
    gemm_tile<1><<<(n + 127) / 128, 256>>>(h, nullptr, nullptr, wt2, nullptr, ps, n);

    // Layer-2 scatter on P (64-wide, half the atomic traffic of scattering h)
    {
        int total = E * 16;
        scatter_kernel<false><<<(total + 255) / 256, 256>>>(ps, C_HID, src, dst, agg2, nullptr, E);
    }

    // out = sigmoid(agg2*invd + S + b2)
    final_kernel<<<(n * 16 + 255) / 256, 256>>>(agg2, ps, deg, b2, out, n);
}

// round 9
// speedup vs baseline: 2.6564x; 1.2729x over previous
#include <cuda_runtime.h>
#include <cuda_bf16.h>
#include <cstdint>

#define NODES_MAX 100000
#define C_IN  64
#define C_HID 128

// ---------------- scratch (static __device__, allocation-free) ----------------
__device__ float g_deg [NODES_MAX];                       // degree -> 1/max(deg,1)
__device__ float g_agg1[(size_t)NODES_MAX * C_IN];
__device__ float g_h   [(size_t)NODES_MAX * C_HID];
__device__ float g_ps  [(size_t)NODES_MAX * C_HID];       // [P | S]
__device__ float g_agg2[(size_t)NODES_MAX * C_IN];
// Weight images: bf16 hi/lo, already in the XOR-swizzled smem layout (straight copy in)
__device__ __align__(16) __nv_bfloat16 g_b1hi[128 * 128];
__device__ __align__(16) __nv_bfloat16 g_b1lo[128 * 128];
__device__ __align__(16) __nv_bfloat16 g_b2hi[128 * 128];
__device__ __align__(16) __nv_bfloat16 g_b2lo[128 * 128];

// ---------------- helpers ----------------
__device__ __forceinline__ uint32_t smem_u32(const void* p) {
    uint32_t a;
    asm("{ .reg .u64 t; cvta.to.shared.u64 t, %1; cvt.u32.u64 %0, t; }" : "=r"(a) : "l"(p));
    return a;
}
__device__ __forceinline__ void sts128(uint32_t addr, uint4 v) {
    asm volatile("st.shared.v4.b32 [%0], {%1,%2,%3,%4};"
                 :: "r"(addr), "r"(v.x), "r"(v.y), "r"(v.z), "r"(v.w));
}
__device__ __forceinline__ void ldsm_x4(uint32_t* r, uint32_t a) {
    asm volatile("ldmatrix.sync.aligned.m8n8.x4.shared.b16 {%0,%1,%2,%3}, [%4];"
                 : "=r"(r[0]), "=r"(r[1]), "=r"(r[2]), "=r"(r[3]) : "r"(a));
}
__device__ __forceinline__ void mma_bf16(float* d, const uint32_t* a, uint32_t b0, uint32_t b1) {
    asm volatile("mma.sync.aligned.m16n8k16.row.col.f32.bf16.bf16.f32 "
                 "{%0,%1,%2,%3}, {%4,%5,%6,%7}, {%8,%9}, {%0,%1,%2,%3};"
                 : "+f"(d[0]), "+f"(d[1]), "+f"(d[2]), "+f"(d[3])
                 : "r"(a[0]), "r"(a[1]), "r"(a[2]), "r"(a[3]), "r"(b0), "r"(b1));
}
// split x,y into bf16 hi pair (returned) and lo pair (out-param)
__device__ __forceinline__ uint32_t bsplit2(float x, float y, uint32_t& lo) {
    __nv_bfloat16 hx = __float2bfloat16_rn(x);
    __nv_bfloat16 hy = __float2bfloat16_rn(y);
    __nv_bfloat16 lx = __float2bfloat16_rn(x - __bfloat162float(hx));
    __nv_bfloat16 ly = __float2bfloat16_rn(y - __bfloat162float(hy));
    lo = ((uint32_t)__bfloat16_as_ushort(ly) << 16) | (uint32_t)__bfloat16_as_ushort(lx);
    return ((uint32_t)__bfloat16_as_ushort(hy) << 16) | (uint32_t)__bfloat16_as_ushort(hx);
}
__device__ __forceinline__ void red_add_v4(float* addr, float4 v) {
    asm volatile("red.global.add.v4.f32 [%0], {%1,%2,%3,%4};"
                 :: "l"(addr), "f"(v.x), "f"(v.y), "f"(v.z), "f"(v.w) : "memory");
}
__device__ __forceinline__ void red_add_f32(float* addr, float v) {
    asm volatile("red.global.add.f32 [%0], %1;" :: "l"(addr), "f"(v) : "memory");
}

// Swizzled byte offset within a [128 rows x 256B] matrix: 16B-chunk XOR with row&7.
__device__ __forceinline__ uint32_t swz(int row, uint32_t kbyte) {
    return (uint32_t)row * 256u + (kbyte ^ (((uint32_t)row & 7u) << 4));
}

// ---------------- weight packing into swizzled bf16 hi/lo images ----------------
// layer1 rows = output channel c: B1[c][k] = k<64 ? W1l[c][k] : W1r[c][k-64]
// layer2 rows = output col of [P|S]: B2[nc][k] = nc<64 ? W2l[nc][k] : W2r[nc-64][k]
__global__ void pack_weights(const float* __restrict__ W1l, const float* __restrict__ W1r,
                             const float* __restrict__ W2l, const float* __restrict__ W2r) {
    int i = blockIdx.x * blockDim.x + threadIdx.x;
    if (i >= 128 * 128) return;
    int nrow = i >> 7, k = i & 127;
    float v1 = (k < 64) ? W1l[nrow * 64 + k] : W1r[nrow * 64 + (k - 64)];
    float v2 = (nrow < 64) ? W2l[nrow * 128 + k] : W2r[(nrow - 64) * 128 + k];
    int e = swz(nrow, (uint32_t)k * 2) >> 1;   // element index in swizzled image
    __nv_bfloat16 h1 = __float2bfloat16_rn(v1);
    __nv_bfloat16 h2 = __float2bfloat16_rn(v2);
    g_b1hi[e] = h1; g_b1lo[e] = __float2bfloat16_rn(v1 - __bfloat162float(h1));
    g_b2hi[e] = h2; g_b2lo[e] = __float2bfloat16_rn(v2 - __bfloat162float(h2));
}

__global__ void invdeg_kernel(float* __restrict__ deg, int n) {
    int i = blockIdx.x * blockDim.x + threadIdx.x;
    if (i < n) deg[i] = 1.0f / fmaxf(deg[i], 1.0f);
}

// ---------------- scatter: one thread per (edge, float4 group), 64-wide rows ----------------
template<bool DO_DEG>
__global__ void scatter_kernel(const float* __restrict__ x, int ld,
                               const int*   __restrict__ src,
                               const int*   __restrict__ dst,
                               float*       __restrict__ agg,
                               float*       __restrict__ deg,
                               int E) {
    int idx = blockIdx.x * blockDim.x + threadIdx.x;
    if (idx >= E * 16) return;
    int e = idx >> 4;
    int q = idx & 15;
    int s = __ldg(&src[e]);
    int d = __ldg(&dst[e]);
    float4 v = *(const float4*)(x + (size_t)s * ld + q * 4);
    red_add_v4(agg + ((size_t)d * 16 + q) * 4, v);
    if (DO_DEG && q == 0) red_add_f32(deg + d, 1.0f);
}

// ---------------- HMMA bf16 split-precision GEMM: out[Mx128] = A_cat[Mx128] @ B^T ----------
// MODE 0 (layer1): A_cat[m][k] = k<64 ? Aa[m][k]*invd[m] : Ab[m][k-64]; epilogue relu(+bias)
// MODE 1 (layer2): A_cat = Aa (128-wide); raw store
// 3-term split: D += AhiBhi + AloBhi + AhiBlo (bf16 hi/lo ≈ 16 mantissa bits).
// B image [n][k] row-major (k contiguous) == mma ".col" layout -> ldmatrix NON-trans.
#define AHI_OFF 0
#define ALO_OFF 32768
#define BHI_OFF 65536
#define BLO_OFF 98304
#define GEMM_SMEM (131072 + 256)

template<int MODE>
__global__ __launch_bounds__(256, 1)
void gemm_mma(const float* __restrict__ Aa,
              const float* __restrict__ Ab,
              const float* __restrict__ invd,
              const __nv_bfloat16* __restrict__ Bhi_g,
              const __nv_bfloat16* __restrict__ Blo_g,
              const float* __restrict__ bias,
              float*       __restrict__ out,
              int n) {
    extern __shared__ char smem_raw[];
    const uint32_t base = (smem_u32(smem_raw) + 255u) & ~255u;
    const int tid   = threadIdx.x;
    const int node0 = blockIdx.x * 128;

    // ---- fill B: straight uint4 copy of pre-swizzled images ----
    {
        const uint4* gh = (const uint4*)Bhi_g;
        const uint4* gl = (const uint4*)Blo_g;
        #pragma unroll
        for (int i = 0; i < 8; i++) {
            int j = tid + i * 256;   // 2048 uint4 per matrix
            sts128(base + BHI_OFF + j * 16, __ldg(gh + j));
            sts128(base + BLO_OFF + j * 16, __ldg(gl + j));
        }
    }
    // ---- fill A: fp32 -> bf16 hi/lo, swizzled, STS.128 ----
    {
        int r = tid & 127;
        int half = tid >> 7;            // 0: k 0-63, 1: k 64-127
        int m = node0 + r;
        const float* sp;
        float sc = 1.f;
        if (MODE == 0) {
            sp = (half ? Ab : Aa) + (size_t)m * 64;
            if (!half && m < n) sc = __ldg(invd + m);
        } else {
            sp = Aa + (size_t)m * 128 + half * 64;
        }
        #pragma unroll
        for (int g = 0; g < 8; g++) {
            float4 v0 = make_float4(0.f, 0.f, 0.f, 0.f);
            float4 v1 = v0;
            if (m < n) {
                v0 = __ldg((const float4*)(sp + g * 8));
                v1 = __ldg((const float4*)(sp + g * 8 + 4));
            }
            v0.x *= sc; v0.y *= sc; v0.z *= sc; v0.w *= sc;
            v1.x *= sc; v1.y *= sc; v1.z *= sc; v1.w *= sc;
            uint4 hi, lo;
            hi.x = bsplit2(v0.x, v0.y, lo.x);
            hi.y = bsplit2(v0.z, v0.w, lo.y);
            hi.z = bsplit2(v1.x, v1.y, lo.z);
            hi.w = bsplit2(v1.z, v1.w, lo.w);
            uint32_t off = swz(r, (uint32_t)(half * 128 + g * 16));
            sts128(base + AHI_OFF + off, hi);
            sts128(base + ALO_OFF + off, lo);
        }
    }
    __syncthreads();

    // ---- MMA mainloop ----
    const int lane = tid & 31, w = tid >> 5;
    float acc[64];
    #pragma unroll
    for (int i = 0; i < 64; i++) acc[i] = 0.f;

    // A frag addressing (m16k16, ldmatrix x4 non-trans, canonical):
    // m0: rows0-7/k0-7, m1: rows8-15/k0-7, m2: rows0-7/k8-15, m3: rows8-15/k8-15
    const int ra      = w * 16 + (lane & 15);
    const uint32_t a_off = base + AHI_OFF + (uint32_t)ra * 256u;
    const uint32_t xa    = ((uint32_t)ra & 7u) << 4;
    const uint32_t kca   = ((uint32_t)(lane >> 4)) << 4;     // 0 or 16 bytes
    // B frag addressing (two n8k16 tiles via x4 non-trans on [n][k] image):
    // m0: n0-7/k0-7, m1: n0-7/k8-15, m2: n8-15/k0-7, m3: n8-15/k8-15
    const int rb0     = (lane & 7) | (((lane >> 4) & 1) << 3);
    const uint32_t b_off = base + BHI_OFF + (uint32_t)rb0 * 256u;
    const uint32_t xb    = ((uint32_t)lane & 7u) << 4;       // rb0&7 == lane&7
    const uint32_t kcb   = (((uint32_t)lane >> 3) & 1u) << 4;

    for (int ks = 0; ks < 8; ks++) {
        uint32_t ah[4], al[4];
        uint32_t ka = ((uint32_t)(ks * 32) + kca) ^ xa;
        ldsm_x4(ah, a_off + ka);
        ldsm_x4(al, a_off + (ALO_OFF - AHI_OFF) + ka);
        uint32_t kb = ((uint32_t)(ks * 32) + kcb) ^ xb;
        #pragma unroll
        for (int p = 0; p < 8; p++) {
            uint32_t bh[4], bl[4];
            uint32_t baddr = b_off + (uint32_t)p * 4096u + kb;
            ldsm_x4(bh, baddr);
            ldsm_x4(bl, baddr + (BLO_OFF - BHI_OFF));
            float* t0 = acc + p * 8;       // n-tile 2p   (b0=bh[0], b1=bh[1])
            float* t1 = acc + p * 8 + 4;   // n-tile 2p+1 (b0=bh[2], b1=bh[3])
            mma_bf16(t0, ah, bh[0], bh[1]);
            mma_bf16(t0, al, bh[0], bh[1]);
            mma_bf16(t0, ah, bl[0], bl[1]);
            mma_bf16(t1, ah, bh[2], bh[3]);
            mma_bf16(t1, al, bh[2], bh[3]);
            mma_bf16(t1, ah, bl[2], bl[3]);
        }
    }

    // ---- epilogue ----
    const int quad = lane >> 2, qt = lane & 3;
    const int r0g = node0 + w * 16 + quad;
    const int r1g = r0g + 8;
    #pragma unroll
    for (int j = 0; j < 16; j++) {
        int c = j * 8 + qt * 2;
        float2 v0 = make_float2(acc[j * 4 + 0], acc[j * 4 + 1]);
        float2 v1 = make_float2(acc[j * 4 + 2], acc[j * 4 + 3]);
        if (MODE == 0) {
            float2 bb = *(const float2*)(bias + c);
            v0.x = fmaxf(v0.x + bb.x, 0.f); v0.y = fmaxf(v0.y + bb.y, 0.f);
            v1.x = fmaxf(v1.x + bb.x, 0.f); v1.y = fmaxf(v1.y + bb.y, 0.f);
        }
        if (r0g < n) *(float2*)(out + (size_t)r0g * 128 + c) = v0;
        if (r1g < n) *(float2*)(out + (size_t)r1g * 128 + c) = v1;
    }
}

// out[m][c] = sigmoid(agg2[m][c]*invd[m] + S[m][c] + b2[c]),  S = PS[:,64:128]
__global__ void final_kernel(const float* __restrict__ agg2,
                             const float* __restrict__ ps,
                             const float* __restrict__ invd,
                             const float* __restrict__ b2,
                             float* __restrict__ out, int n) {
    int idx = blockIdx.x * blockDim.x + threadIdx.x;
    if (idx >= n * 16) return;
    int m = idx >> 4;
    int q = (idx & 15) * 4;
    float iv = __ldg(&invd[m]);
    float4 a = *(const float4*)(agg2 + (size_t)m * 64 + q);
    float4 s = *(const float4*)(ps + (size_t)m * 128 + 64 + q);
    float4 b = *(const float4*)(b2 + q);
    float4 r;
    r.x = 1.0f / (1.0f + __expf(-(a.x * iv + s.x + b.x)));
    r.y = 1.0f / (1.0f + __expf(-(a.y * iv + s.y + b.y)));
    r.z = 1.0f / (1.0f + __expf(-(a.z * iv + s.z + b.z)));
    r.w = 1.0f / (1.0f + __expf(-(a.w * iv + s.w + b.w)));
    *(float4*)(out + (size_t)m * 64 + q) = r;
}

extern "C" void kernel_launch(void* const* d_in, const int* in_sizes, int n_in,
                              void* d_out, int out_size) {
    const float* x   = (const float*)d_in[0];
    const int*   ei  = (const int*)  d_in[1];
    const float* W1l = (const float*)d_in[2];
    const float* W1r = (const float*)d_in[3];
    const float* b1  = (const float*)d_in[4];
    const float* W2l = (const float*)d_in[5];
    const float* W2r = (const float*)d_in[6];
    const float* b2  = (const float*)d_in[7];
    float* out = (float*)d_out;

    const int n = in_sizes[0] / C_IN;
    const int E = in_sizes[1] / 2;
    const int* src = ei;
    const int* dst = ei + E;

    float *deg, *agg1, *h, *ps, *agg2;
    __nv_bfloat16 *b1hi, *b1lo, *b2hi, *b2lo;
    cudaGetSymbolAddress((void**)&deg,  g_deg);
    cudaGetSymbolAddress((void**)&agg1, g_agg1);
    cudaGetSymbolAddress((void**)&h,    g_h);
    cudaGetSymbolAddress((void**)&ps,   g_ps);
    cudaGetSymbolAddress((void**)&agg2, g_agg2);
    cudaGetSymbolAddress((void**)&b1hi, g_b1hi);
    cudaGetSymbolAddress((void**)&b1lo, g_b1lo);
    cudaGetSymbolAddress((void**)&b2hi, g_b2hi);
    cudaGetSymbolAddress((void**)&b2lo, g_b2lo);

    cudaFuncSetAttribute(gemm_mma<0>, cudaFuncAttributeMaxDynamicSharedMemorySize, GEMM_SMEM);
    cudaFuncSetAttribute(gemm_mma<1>, cudaFuncAttributeMaxDynamicSharedMemorySize, GEMM_SMEM);

    cudaMemsetAsync(deg,  0, (size_t)n * sizeof(float));
    cudaMemsetAsync(agg1, 0, (size_t)n * C_IN * sizeof(float));
    cudaMemsetAsync(agg2, 0, (size_t)n * C_IN * sizeof(float));

    pack_weights<<<64, 256>>>(W1l, W1r, W2l, W2r);

    // layer-1 scatter (+degree); x is 64-wide
    scatter_kernel<true><<<(E * 16 + 255) / 256, 256>>>(x, C_IN, src, dst, agg1, deg, E);
    invdeg_kernel<<<(n + 255) / 256, 256>>>(deg, n);

    const int tiles = (n + 127) / 128;
    // layer 1: h = relu([agg1*invd | x] @ B1^T + b1)
    gemm_mma<0><<<tiles, 256, GEMM_SMEM>>>(agg1, x, deg, b1hi, b1lo, b1, h, n);
    // layer 2 dense first (linearity of mean): PS = h @ [W2l ; W2r]^T
    gemm_mma<1><<<tiles, 256, GEMM_SMEM>>>(h, nullptr, nullptr, b2hi, b2lo, nullptr, ps, n);

    // layer-2 scatter on P (64-wide)
    scatter_kernel<false><<<(E * 16 + 255) / 256, 256>>>(ps, C_HID, src, dst, agg2, nullptr, E);

    // out = sigmoid(agg2*invd + S + b2)
    final_kernel<<<(n * 16 + 255) / 256, 256>>>(agg2, ps, deg, b2, out, n);
}

// round 13
// speedup vs baseline: 3.5897x; 1.3514x over previous
#include <cuda_runtime.h>
#include <cuda_bf16.h>
#include <cstdint>

#define NODES_MAX 100000
#define EDGES_MAX 1600000
#define C_IN  64
#define C_HID 128

// ---------------- scratch (static __device__, allocation-free) ----------------
__device__ float g_invd[NODES_MAX];                       // 1/max(deg,1)
__device__ int   g_cnt  [NODES_MAX];                      // degree counts
__device__ int   g_start[NODES_MAX];                      // CSR offsets
__device__ int   g_cur  [NODES_MAX];                      // permute cursors
__device__ int   g_csrc [EDGES_MAX];                      // src ids grouped by dst
__device__ int   g_bsum [512];                            // scan block sums
__device__ float g_agg1[(size_t)NODES_MAX * C_IN];
__device__ float g_h   [(size_t)NODES_MAX * C_HID];
__device__ float g_ps  [(size_t)NODES_MAX * C_HID];       // [P | S]
__device__ float g_agg2[(size_t)NODES_MAX * C_IN];
// Weight images: bf16 hi/lo, already in the XOR-swizzled smem layout (straight copy in)
__device__ __align__(16) __nv_bfloat16 g_b1hi[128 * 128];
__device__ __align__(16) __nv_bfloat16 g_b1lo[128 * 128];
__device__ __align__(16) __nv_bfloat16 g_b2hi[128 * 128];
__device__ __align__(16) __nv_bfloat16 g_b2lo[128 * 128];

// ---------------- helpers ----------------
__device__ __forceinline__ uint32_t smem_u32(const void* p) {
    uint32_t a;
    asm("{ .reg .u64 t; cvta.to.shared.u64 t, %1; cvt.u32.u64 %0, t; }" : "=r"(a) : "l"(p));
    return a;
}
__device__ __forceinline__ void sts128(uint32_t addr, uint4 v) {
    asm volatile("st.shared.v4.b32 [%0], {%1,%2,%3,%4};"
                 :: "r"(addr), "r"(v.x), "r"(v.y), "r"(v.z), "r"(v.w));
}
__device__ __forceinline__ void ldsm_x4(uint32_t* r, uint32_t a) {
    asm volatile("ldmatrix.sync.aligned.m8n8.x4.shared.b16 {%0,%1,%2,%3}, [%4];"
                 : "=r"(r[0]), "=r"(r[1]), "=r"(r[2]), "=r"(r[3]) : "r"(a));
}
__device__ __forceinline__ void mma_bf16(float* d, const uint32_t* a, uint32_t b0, uint32_t b1) {
    asm volatile("mma.sync.aligned.m16n8k16.row.col.f32.bf16.bf16.f32 "
                 "{%0,%1,%2,%3}, {%4,%5,%6,%7}, {%8,%9}, {%0,%1,%2,%3};"
                 : "+f"(d[0]), "+f"(d[1]), "+f"(d[2]), "+f"(d[3])
                 : "r"(a[0]), "r"(a[1]), "r"(a[2]), "r"(a[3]), "r"(b0), "r"(b1));
}
__device__ __forceinline__ uint32_t bsplit2(float x, float y, uint32_t& lo) {
    __nv_bfloat16 hx = __float2bfloat16_rn(x);
    __nv_bfloat16 hy = __float2bfloat16_rn(y);
    __nv_bfloat16 lx = __float2bfloat16_rn(x - __bfloat162float(hx));
    __nv_bfloat16 ly = __float2bfloat16_rn(y - __bfloat162float(hy));
    lo = ((uint32_t)__bfloat16_as_ushort(ly) << 16) | (uint32_t)__bfloat16_as_ushort(lx);
    return ((uint32_t)__bfloat16_as_ushort(hy) << 16) | (uint32_t)__bfloat16_as_ushort(hx);
}

// Swizzled byte offset within a [128 rows x 256B] matrix: 16B-chunk XOR with row&7.
__device__ __forceinline__ uint32_t swz(int row, uint32_t kbyte) {
    return (uint32_t)row * 256u + (kbyte ^ (((uint32_t)row & 7u) << 4));
}

// ---------------- weight packing into swizzled bf16 hi/lo images ----------------
__global__ void pack_weights(const float* __restrict__ W1l, const float* __restrict__ W1r,
                             const float* __restrict__ W2l, const float* __restrict__ W2r) {
    int i = blockIdx.x * blockDim.x + threadIdx.x;
    if (i >= 128 * 128) return;
    int nrow = i >> 7, k = i & 127;
    float v1 = (k < 64) ? W1l[nrow * 64 + k] : W1r[nrow * 64 + (k - 64)];
    float v2 = (nrow < 64) ? W2l[nrow * 128 + k] : W2r[(nrow - 64) * 128 + k];
    int e = swz(nrow, (uint32_t)k * 2) >> 1;
    __nv_bfloat16 h1 = __float2bfloat16_rn(v1);
    __nv_bfloat16 h2 = __float2bfloat16_rn(v2);
    g_b1hi[e] = h1; g_b1lo[e] = __float2bfloat16_rn(v1 - __bfloat162float(h1));
    g_b2hi[e] = h2; g_b2lo[e] = __float2bfloat16_rn(v2 - __bfloat162float(h2));
}

// ---------------- CSR build ----------------
__global__ void hist_kernel(const int* __restrict__ dst, int* __restrict__ cnt, int E) {
    int e = blockIdx.x * blockDim.x + threadIdx.x;
    if (e < E) atomicAdd(&cnt[__ldg(&dst[e])], 1);
}

// pass1: per-1024-block totals
__global__ void scan_pass1(const int* __restrict__ cnt, int* __restrict__ bsum, int n) {
    __shared__ int ws[8];
    int base = blockIdx.x * 1024 + threadIdx.x * 4;
    int s = 0;
    #pragma unroll
    for (int i = 0; i < 4; i++) { int idx = base + i; if (idx < n) s += __ldg(&cnt[idx]); }
    for (int o = 16; o; o >>= 1) s += __shfl_down_sync(~0u, s, o);
    if ((threadIdx.x & 31) == 0) ws[threadIdx.x >> 5] = s;
    __syncthreads();
    if (threadIdx.x < 8) {
        int v = ws[threadIdx.x];
        for (int o = 4; o; o >>= 1) v += __shfl_down_sync(0xff, v, o);
        if (threadIdx.x == 0) bsum[blockIdx.x] = v;
    }
}
// pass2: exclusive scan of block totals (nb <= 512), single block
__global__ void scan_pass2(int* __restrict__ bsum, int nb) {
    __shared__ int sm[512];
    int t = threadIdx.x;
    int v = (t < nb) ? bsum[t] : 0;
    sm[t] = v;
    __syncthreads();
    for (int o = 1; o < 512; o <<= 1) {
        int u = (t >= o) ? sm[t - o] : 0;
        __syncthreads();
        sm[t] += u;
        __syncthreads();
    }
    if (t < nb) bsum[t] = sm[t] - v;   // exclusive
}
// pass3: full exclusive scan -> start/cursor, plus invdeg
__global__ void scan_pass3(const int* __restrict__ cnt, const int* __restrict__ bsum,
                           int* __restrict__ start, int* __restrict__ cur,
                           float* __restrict__ invd, int n) {
    __shared__ int wsum[8];
    int t = threadIdx.x;
    int base = blockIdx.x * 1024 + t * 4;
    int c[4]; int s = 0;
    #pragma unroll
    for (int i = 0; i < 4; i++) { int idx = base + i; c[i] = (idx < n) ? __ldg(&cnt[idx]) : 0; s += c[i]; }
    int lane = t & 31, w = t >> 5;
    int incl = s;
    for (int o = 1; o < 32; o <<= 1) { int u = __shfl_up_sync(~0u, incl, o); if (lane >= o) incl += u; }
    int excl = incl - s;
    if (lane == 31) wsum[w] = incl;
    __syncthreads();
    if (t < 8) {
        int v = wsum[t], iv = v;
        for (int o = 1; o < 8; o <<= 1) { int u = __shfl_up_sync(0xff, iv, o); if (t >= o) iv += u; }
        wsum[t] = iv - v;
    }
    __syncthreads();
    int off = bsum[blockIdx.x] + wsum[w] + excl;
    #pragma unroll
    for (int i = 0; i < 4; i++) {
        int idx = base + i;
        if (idx < n) {
            start[idx] = off;
            cur[idx]   = off;
            invd[idx]  = 1.0f / fmaxf((float)c[i], 1.0f);
            off += c[i];
        }
    }
}
__global__ void permute_kernel(const int* __restrict__ src, const int* __restrict__ dst,
                               int* __restrict__ cur, int* __restrict__ csrc, int E) {
    int e = blockIdx.x * blockDim.x + threadIdx.x;
    if (e < E) {
        int d = __ldg(&dst[e]);
        int slot = atomicAdd(&cur[d], 1);
        csrc[slot] = __ldg(&src[e]);
    }
}

// ---------------- CSR aggregation: agg[node][0:64] = sum_{j in N(node)} x[src_j][0:64] ---------
// 16 threads per node, one float4 lane each (coalesced 256B per neighbor). No atomics.
__global__ void agg_csr(const float* __restrict__ x, int ld,
                        const int* __restrict__ csrc,
                        const int* __restrict__ start,
                        const int* __restrict__ cnt,
                        float* __restrict__ agg, int n) {
    int tid = blockIdx.x * blockDim.x + threadIdx.x;
    int node = tid >> 4;
    if (node >= n) return;
    int q = tid & 15;
    int s0 = __ldg(&start[node]);
    int c  = __ldg(&cnt[node]);
    float4 acc = make_float4(0.f, 0.f, 0.f, 0.f);
    int j = 0;
    for (; j + 4 <= c; j += 4) {
        int sa = __ldg(&csrc[s0 + j]);
        int sb = __ldg(&csrc[s0 + j + 1]);
        int sc = __ldg(&csrc[s0 + j + 2]);
        int sd = __ldg(&csrc[s0 + j + 3]);
        float4 va = __ldg((const float4*)(x + (size_t)sa * ld) + q);
        float4 vb = __ldg((const float4*)(x + (size_t)sb * ld) + q);
        float4 vc = __ldg((const float4*)(x + (size_t)sc * ld) + q);
        float4 vd = __ldg((const float4*)(x + (size_t)sd * ld) + q);
        acc.x += va.x + vb.x + vc.x + vd.x;
        acc.y += va.y + vb.y + vc.y + vd.y;
        acc.z += va.z + vb.z + vc.z + vd.z;
        acc.w += va.w + vb.w + vc.w + vd.w;
    }
    for (; j < c; j++) {
        int s = __ldg(&csrc[s0 + j]);
        float4 v = __ldg((const float4*)(x + (size_t)s * ld) + q);
        acc.x += v.x; acc.y += v.y; acc.z += v.z; acc.w += v.w;
    }
    ((float4*)agg)[(size_t)node * 16 + q] = acc;
}

// ---------------- HMMA bf16 split-precision GEMM (unchanged from R9) ----------
#define AHI_OFF 0
#define ALO_OFF 32768
#define BHI_OFF 65536
#define BLO_OFF 98304
#define GEMM_SMEM (131072 + 256)

template<int MODE>
__global__ __launch_bounds__(256, 1)
void gemm_mma(const float* __restrict__ Aa,
              const float* __restrict__ Ab,
              const float* __restrict__ invd,
              const __nv_bfloat16* __restrict__ Bhi_g,
              const __nv_bfloat16* __restrict__ Blo_g,
              const float* __restrict__ bias,
              float*       __restrict__ out,
              int n) {
    extern __shared__ char smem_raw[];
    const uint32_t base = (smem_u32(smem_raw) + 255u) & ~255u;
    const int tid   = threadIdx.x;
    const int node0 = blockIdx.x * 128;

    // ---- fill B: straight uint4 copy of pre-swizzled images ----
    {
        const uint4* gh = (const uint4*)Bhi_g;
        const uint4* gl = (const uint4*)Blo_g;
        #pragma unroll
        for (int i = 0; i < 8; i++) {
            int j = tid + i * 256;
            sts128(base + BHI_OFF + j * 16, __ldg(gh + j));
            sts128(base + BLO_OFF + j * 16, __ldg(gl + j));
        }
    }
    // ---- fill A: fp32 -> bf16 hi/lo, swizzled, STS.128 ----
    {
        int r = tid & 127;
        int half = tid >> 7;
        int m = node0 + r;
        const float* sp;
        float sc = 1.f;
        if (MODE == 0) {
            sp = (half ? Ab : Aa) + (size_t)m * 64;
            if (!half && m < n) sc = __ldg(invd + m);
        } else {
            sp = Aa + (size_t)m * 128 + half * 64;
        }
        #pragma unroll
        for (int g = 0; g < 8; g++) {
            float4 v0 = make_float4(0.f, 0.f, 0.f, 0.f);
            float4 v1 = v0;
            if (m < n) {
                v0 = __ldg((const float4*)(sp + g * 8));
                v1 = __ldg((const float4*)(sp + g * 8 + 4));
            }
            v0.x *= sc; v0.y *= sc; v0.z *= sc; v0.w *= sc;
            v1.x *= sc; v1.y *= sc; v1.z *= sc; v1.w *= sc;
            uint4 hi, lo;
            hi.x = bsplit2(v0.x, v0.y, lo.x);
            hi.y = bsplit2(v0.z, v0.w, lo.y);
            hi.z = bsplit2(v1.x, v1.y, lo.z);
            hi.w = bsplit2(v1.z, v1.w, lo.w);
            uint32_t off = swz(r, (uint32_t)(half * 128 + g * 16));
            sts128(base + AHI_OFF + off, hi);
            sts128(base + ALO_OFF + off, lo);
        }
    }
    __syncthreads();

    // ---- MMA mainloop ----
    const int lane = tid & 31, w = tid >> 5;
    float acc[64];
    #pragma unroll
    for (int i = 0; i < 64; i++) acc[i] = 0.f;

    const int ra      = w * 16 + (lane & 15);
    const uint32_t a_off = base + AHI_OFF + (uint32_t)ra * 256u;
    const uint32_t xa    = ((uint32_t)ra & 7u) << 4;
    const uint32_t kca   = ((uint32_t)(lane >> 4)) << 4;
    const int rb0     = (lane & 7) | (((lane >> 4) & 1) << 3);
    const uint32_t b_off = base + BHI_OFF + (uint32_t)rb0 * 256u;
    const uint32_t xb    = ((uint32_t)lane & 7u) << 4;
    const uint32_t kcb   = (((uint32_t)lane >> 3) & 1u) << 4;

    for (int ks = 0; ks < 8; ks++) {
        uint32_t ah[4], al[4];
        uint32_t ka = ((uint32_t)(ks * 32) + kca) ^ xa;
        ldsm_x4(ah, a_off + ka);
        ldsm_x4(al, a_off + (ALO_OFF - AHI_OFF) + ka);
        uint32_t kb = ((uint32_t)(ks * 32) + kcb) ^ xb;
        #pragma unroll
        for (int p = 0; p < 8; p++) {
            uint32_t bh[4], bl[4];
            uint32_t baddr = b_off + (uint32_t)p * 4096u + kb;
            ldsm_x4(bh, baddr);
            ldsm_x4(bl, baddr + (BLO_OFF - BHI_OFF));
            float* t0 = acc + p * 8;
            float* t1 = acc + p * 8 + 4;
            mma_bf16(t0, ah, bh[0], bh[1]);
            mma_bf16(t0, al, bh[0], bh[1]);
            mma_bf16(t0, ah, bl[0], bl[1]);
            mma_bf16(t1, ah, bh[2], bh[3]);
            mma_bf16(t1, al, bh[2], bh[3]);
            mma_bf16(t1, ah, bl[2], bl[3]);
        }
    }

    // ---- epilogue ----
    const int quad = lane >> 2, qt = lane & 3;
    const int r0g = node0 + w * 16 + quad;
    const int r1g = r0g + 8;
    #pragma unroll
    for (int j = 0; j < 16; j++) {
        int c = j * 8 + qt * 2;
        float2 v0 = make_float2(acc[j * 4 + 0], acc[j * 4 + 1]);
        float2 v1 = make_float2(acc[j * 4 + 2], acc[j * 4 + 3]);
        if (MODE == 0) {
            float2 bb = *(const float2*)(bias + c);
            v0.x = fmaxf(v0.x + bb.x, 0.f); v0.y = fmaxf(v0.y + bb.y, 0.f);
            v1.x = fmaxf(v1.x + bb.x, 0.f); v1.y = fmaxf(v1.y + bb.y, 0.f);
        }
        if (r0g < n) *(float2*)(out + (size_t)r0g * 128 + c) = v0;
        if (r1g < n) *(float2*)(out + (size_t)r1g * 128 + c) = v1;
    }
}

// out[m][c] = sigmoid(agg2[m][c]*invd[m] + S[m][c] + b2[c]),  S = PS[:,64:128]
__global__ void final_kernel(const float* __restrict__ agg2,
                             const float* __restrict__ ps,
                             const float* __restrict__ invd,
                             const float* __restrict__ b2,
                             float* __restrict__ out, int n) {
    int idx = blockIdx.x * blockDim.x + threadIdx.x;
    if (idx >= n * 16) return;
    int m = idx >> 4;
    int q = (idx & 15) * 4;
    float iv = __ldg(&invd[m]);
    float4 a = *(const float4*)(agg2 + (size_t)m * 64 + q);
    float4 s = *(const float4*)(ps + (size_t)m * 128 + 64 + q);
    float4 b = *(const float4*)(b2 + q);
    float4 r;
    r.x = 1.0f / (1.0f + __expf(-(a.x * iv + s.x + b.x)));
    r.y = 1.0f / (1.0f + __expf(-(a.y * iv + s.y + b.y)));
    r.z = 1.0f / (1.0f + __expf(-(a.z * iv + s.z + b.z)));
    r.w = 1.0f / (1.0f + __expf(-(a.w * iv + s.w + b.w)));
    *(float4*)(out + (size_t)m * 64 + q) = r;
}

extern "C" void kernel_launch(void* const* d_in, const int* in_sizes, int n_in,
                              void* d_out, int out_size) {
    const float* x   = (const float*)d_in[0];
    const int*   ei  = (const int*)  d_in[1];
    const float* W1l = (const float*)d_in[2];
    const float* W1r = (const float*)d_in[3];
    const float* b1  = (const float*)d_in[4];
    const float* W2l = (const float*)d_in[5];
    const float* W2r = (const float*)d_in[6];
    const float* b2  = (const float*)d_in[7];
    float* out = (float*)d_out;

    const int n = in_sizes[0] / C_IN;
    const int E = in_sizes[1] / 2;
    const int* src = ei;
    const int* dst = ei + E;

    float *invd, *agg1, *h, *ps, *agg2;
    int *cnt, *startp, *cur, *csrc, *bsum;
    __nv_bfloat16 *b1hi, *b1lo, *b2hi, *b2lo;
    cudaGetSymbolAddress((void**)&invd,  g_invd);
    cudaGetSymbolAddress((void**)&cnt,   g_cnt);
    cudaGetSymbolAddress((void**)&startp,g_start);
    cudaGetSymbolAddress((void**)&cur,   g_cur);
    cudaGetSymbolAddress((void**)&csrc,  g_csrc);
    cudaGetSymbolAddress((void**)&bsum,  g_bsum);
    cudaGetSymbolAddress((void**)&agg1,  g_agg1);
    cudaGetSymbolAddress((void**)&h,     g_h);
    cudaGetSymbolAddress((void**)&ps,    g_ps);
    cudaGetSymbolAddress((void**)&agg2,  g_agg2);
    cudaGetSymbolAddress((void**)&b1hi,  g_b1hi);
    cudaGetSymbolAddress((void**)&b1lo,  g_b1lo);
    cudaGetSymbolAddress((void**)&b2hi,  g_b2hi);
    cudaGetSymbolAddress((void**)&b2lo,  g_b2lo);

    cudaFuncSetAttribute(gemm_mma<0>, cudaFuncAttributeMaxDynamicSharedMemorySize, GEMM_SMEM);
    cudaFuncSetAttribute(gemm_mma<1>, cudaFuncAttributeMaxDynamicSharedMemorySize, GEMM_SMEM);

    cudaMemsetAsync(cnt, 0, (size_t)n * sizeof(int));
    pack_weights<<<64, 256>>>(W1l, W1r, W2l, W2r);

    // ---- CSR build (once, reused by both layers) ----
    const int nb = (n + 1023) / 1024;
    hist_kernel<<<(E + 255) / 256, 256>>>(dst, cnt, E);
    scan_pass1<<<nb, 256>>>(cnt, bsum, n);
    scan_pass2<<<1, 512>>>(bsum, nb);
    scan_pass3<<<nb, 256>>>(cnt, bsum, startp, cur, invd, n);
    permute_kernel<<<(E + 255) / 256, 256>>>(src, dst, cur, csrc, E);

    // ---- layer 1 ----
    agg_csr<<<(n * 16 + 255) / 256, 256>>>(x, C_IN, csrc, startp, cnt, agg1, n);
    const int tiles = (n + 127) / 128;
    gemm_mma<0><<<tiles, 256, GEMM_SMEM>>>(agg1, x, invd, b1hi, b1lo, b1, h, n);

    // ---- layer 2 (dense first via linearity of mean) ----
    gemm_mma<1><<<tiles, 256, GEMM_SMEM>>>(h, nullptr, nullptr, b2hi, b2lo, nullptr, ps, n);
    agg_csr<<<(n * 16 + 255) / 256, 256>>>(ps, C_HID, csrc, startp, cnt, agg2, n);

    // ---- epilogue ----
    final_kernel<<<(n * 16 + 255) / 256, 256>>>(agg2, ps, invd, b2, out, n);
}

// round 14
// speedup vs baseline: 3.6122x; 1.0063x over previous
#include <cuda_runtime.h>
#include <cuda_bf16.h>
#include <cstdint>

#define NODES_MAX 100000
#define EDGES_MAX 1600000
#define C_IN  64
#define C_HID 128

// ---------------- scratch (static __device__, allocation-free) ----------------
__device__ float g_invd[NODES_MAX];                       // 1/max(deg,1)
__device__ int   g_cnt  [NODES_MAX];                      // degree counts
__device__ int   g_start[NODES_MAX];                      // CSR offsets
__device__ int   g_cur  [NODES_MAX];                      // permute cursors
__device__ int   g_csrc [EDGES_MAX];                      // src ids grouped by dst
__device__ int   g_bsum [512];                            // scan block sums
__device__ float g_agg1[(size_t)NODES_MAX * C_IN];
__device__ float g_h   [(size_t)NODES_MAX * C_HID];
__device__ float g_ps  [(size_t)NODES_MAX * C_HID];       // [P | S]
__device__ float g_agg2[(size_t)NODES_MAX * C_IN];
// Weight images: bf16 hi/lo, already in the XOR-swizzled smem layout (straight copy in)
__device__ __align__(16) __nv_bfloat16 g_b1hi[128 * 128];
__device__ __align__(16) __nv_bfloat16 g_b1lo[128 * 128];
__device__ __align__(16) __nv_bfloat16 g_b2hi[128 * 128];
__device__ __align__(16) __nv_bfloat16 g_b2lo[128 * 128];

// ---------------- helpers ----------------
__device__ __forceinline__ uint32_t smem_u32(const void* p) {
    uint32_t a;
    asm("{ .reg .u64 t; cvta.to.shared.u64 t, %1; cvt.u32.u64 %0, t; }" : "=r"(a) : "l"(p));
    return a;
}
__device__ __forceinline__ void sts128(uint32_t addr, uint4 v) {
    asm volatile("st.shared.v4.b32 [%0], {%1,%2,%3,%4};"
                 :: "r"(addr), "r"(v.x), "r"(v.y), "r"(v.z), "r"(v.w));
}
__device__ __forceinline__ void ldsm_x4(uint32_t* r, uint32_t a) {
    asm volatile("ldmatrix.sync.aligned.m8n8.x4.shared.b16 {%0,%1,%2,%3}, [%4];"
                 : "=r"(r[0]), "=r"(r[1]), "=r"(r[2]), "=r"(r[3]) : "r"(a));
}
__device__ __forceinline__ void mma_bf16(float* d, const uint32_t* a, uint32_t b0, uint32_t b1) {
    asm volatile("mma.sync.aligned.m16n8k16.row.col.f32.bf16.bf16.f32 "
                 "{%0,%1,%2,%3}, {%4,%5,%6,%7}, {%8,%9}, {%0,%1,%2,%3};"
                 : "+f"(d[0]), "+f"(d[1]), "+f"(d[2]), "+f"(d[3])
                 : "r"(a[0]), "r"(a[1]), "r"(a[2]), "r"(a[3]), "r"(b0), "r"(b1));
}
__device__ __forceinline__ uint32_t bsplit2(float x, float y, uint32_t& lo) {
    __nv_bfloat16 hx = __float2bfloat16_rn(x);
    __nv_bfloat16 hy = __float2bfloat16_rn(y);
    __nv_bfloat16 lx = __float2bfloat16_rn(x - __bfloat162float(hx));
    __nv_bfloat16 ly = __float2bfloat16_rn(y - __bfloat162float(hy));
    lo = ((uint32_t)__bfloat16_as_ushort(ly) << 16) | (uint32_t)__bfloat16_as_ushort(lx);
    return ((uint32_t)__bfloat16_as_ushort(hy) << 16) | (uint32_t)__bfloat16_as_ushort(hx);
}

// Swizzled byte offset within a [128 rows x 256B] matrix: 16B-chunk XOR with row&7.
__device__ __forceinline__ uint32_t swz(int row, uint32_t kbyte) {
    return (uint32_t)row * 256u + (kbyte ^ (((uint32_t)row & 7u) << 4));
}

// ---------------- weight packing into swizzled bf16 hi/lo images ----------------
__global__ void pack_weights(const float* __restrict__ W1l, const float* __restrict__ W1r,
                             const float* __restrict__ W2l, const float* __restrict__ W2r) {
    int i = blockIdx.x * blockDim.x + threadIdx.x;
    if (i >= 128 * 128) return;
    int nrow = i >> 7, k = i & 127;
    float v1 = (k < 64) ? W1l[nrow * 64 + k] : W1r[nrow * 64 + (k - 64)];
    float v2 = (nrow < 64) ? W2l[nrow * 128 + k] : W2r[(nrow - 64) * 128 + k];
    int e = swz(nrow, (uint32_t)k * 2) >> 1;
    __nv_bfloat16 h1 = __float2bfloat16_rn(v1);
    __nv_bfloat16 h2 = __float2bfloat16_rn(v2);
    g_b1hi[e] = h1; g_b1lo[e] = __float2bfloat16_rn(v1 - __bfloat162float(h1));
    g_b2hi[e] = h2; g_b2lo[e] = __float2bfloat16_rn(v2 - __bfloat162float(h2));
}

// ---------------- CSR build ----------------
__global__ void hist_kernel(const int* __restrict__ dst, int* __restrict__ cnt, int E) {
    int e = blockIdx.x * blockDim.x + threadIdx.x;
    if (e < E) atomicAdd(&cnt[__ldg(&dst[e])], 1);
}

__global__ void scan_pass1(const int* __restrict__ cnt, int* __restrict__ bsum, int n) {
    __shared__ int ws[8];
    int base = blockIdx.x * 1024 + threadIdx.x * 4;
    int s = 0;
    #pragma unroll
    for (int i = 0; i < 4; i++) { int idx = base + i; if (idx < n) s += __ldg(&cnt[idx]); }
    for (int o = 16; o; o >>= 1) s += __shfl_down_sync(~0u, s, o);
    if ((threadIdx.x & 31) == 0) ws[threadIdx.x >> 5] = s;
    __syncthreads();
    if (threadIdx.x < 8) {
        int v = ws[threadIdx.x];
        for (int o = 4; o; o >>= 1) v += __shfl_down_sync(0xff, v, o);
        if (threadIdx.x == 0) bsum[blockIdx.x] = v;
    }
}
__global__ void scan_pass2(int* __restrict__ bsum, int nb) {
    __shared__ int sm[512];
    int t = threadIdx.x;
    int v = (t < nb) ? bsum[t] : 0;
    sm[t] = v;
    __syncthreads();
    for (int o = 1; o < 512; o <<= 1) {
        int u = (t >= o) ? sm[t - o] : 0;
        __syncthreads();
        sm[t] += u;
        __syncthreads();
    }
    if (t < nb) bsum[t] = sm[t] - v;   // exclusive
}
__global__ void scan_pass3(const int* __restrict__ cnt, const int* __restrict__ bsum,
                           int* __restrict__ start, int* __restrict__ cur,
                           float* __restrict__ invd, int n) {
    __shared__ int wsum[8];
    int t = threadIdx.x;
    int base = blockIdx.x * 1024 + t * 4;
    int c[4]; int s = 0;
    #pragma unroll
    for (int i = 0; i < 4; i++) { int idx = base + i; c[i] = (idx < n) ? __ldg(&cnt[idx]) : 0; s += c[i]; }
    int lane = t & 31, w = t >> 5;
    int incl = s;
    for (int o = 1; o < 32; o <<= 1) { int u = __shfl_up_sync(~0u, incl, o); if (lane >= o) incl += u; }
    int excl = incl - s;
    if (lane == 31) wsum[w] = incl;
    __syncthreads();
    if (t < 8) {
        int v = wsum[t], iv = v;
        for (int o = 1; o < 8; o <<= 1) { int u = __shfl_up_sync(0xff, iv, o); if (t >= o) iv += u; }
        wsum[t] = iv - v;
    }
    __syncthreads();
    int off = bsum[blockIdx.x] + wsum[w] + excl;
    #pragma unroll
    for (int i = 0; i < 4; i++) {
        int idx = base + i;
        if (idx < n) {
            start[idx] = off;
            cur[idx]   = off;
            invd[idx]  = 1.0f / fmaxf((float)c[i], 1.0f);
            off += c[i];
        }
    }
}
__global__ void permute_kernel(const int* __restrict__ src, const int* __restrict__ dst,
                               int* __restrict__ cur, int* __restrict__ csrc, int E) {
    int e = blockIdx.x * blockDim.x + threadIdx.x;
    if (e < E) {
        int d = __ldg(&dst[e]);
        int slot = atomicAdd(&cur[d], 1);
        csrc[slot] = __ldg(&src[e]);
    }
}

// ---------------- CSR aggregation (no atomics) ----------------
__global__ void agg_csr(const float* __restrict__ x, int ld,
                        const int* __restrict__ csrc,
                        const int* __restrict__ start,
                        const int* __restrict__ cnt,
                        float* __restrict__ agg, int n) {
    int tid = blockIdx.x * blockDim.x + threadIdx.x;
    int node = tid >> 4;
    if (node >= n) return;
    int q = tid & 15;
    int s0 = __ldg(&start[node]);
    int c  = __ldg(&cnt[node]);
    float4 acc = make_float4(0.f, 0.f, 0.f, 0.f);
    int j = 0;
    for (; j + 4 <= c; j += 4) {
        int sa = __ldg(&csrc[s0 + j]);
        int sb = __ldg(&csrc[s0 + j + 1]);
        int sc = __ldg(&csrc[s0 + j + 2]);
        int sd = __ldg(&csrc[s0 + j + 3]);
        float4 va = __ldg((const float4*)(x + (size_t)sa * ld) + q);
        float4 vb = __ldg((const float4*)(x + (size_t)sb * ld) + q);
        float4 vc = __ldg((const float4*)(x + (size_t)sc * ld) + q);
        float4 vd = __ldg((const float4*)(x + (size_t)sd * ld) + q);
        acc.x += va.x + vb.x + vc.x + vd.x;
        acc.y += va.y + vb.y + vc.y + vd.y;
        acc.z += va.z + vb.z + vc.z + vd.z;
        acc.w += va.w + vb.w + vc.w + vd.w;
    }
    for (; j < c; j++) {
        int s = __ldg(&csrc[s0 + j]);
        float4 v = __ldg((const float4*)(x + (size_t)s * ld) + q);
        acc.x += v.x; acc.y += v.y; acc.z += v.z; acc.w += v.w;
    }
    ((float4*)agg)[(size_t)node * 16 + q] = acc;
}

// ---------------- HMMA bf16 split-precision GEMM: out[Mx128] = A_cat[Mx128] @ B^T ----------
// Warp tiling m32 x n64 (8 warps = 4m x 2n over the 128x128 block tile):
// per K-step: 4 A-ldsm + 8 B-ldsm vs 48 mma (was 18 ldsm) -> LDSM-pressure cut 33%.
#define AHI_OFF 0
#define ALO_OFF 32768
#define BHI_OFF 65536
#define BLO_OFF 98304
#define GEMM_SMEM (131072 + 256)

template<int MODE>
__global__ __launch_bounds__(256, 1)
void gemm_mma(const float* __restrict__ Aa,
              const float* __restrict__ Ab,
              const float* __restrict__ invd,
              const __nv_bfloat16* __restrict__ Bhi_g,
              const __nv_bfloat16* __restrict__ Blo_g,
              const float* __restrict__ bias,
              float*       __restrict__ out,
              int n) {
    extern __shared__ char smem_raw[];
    const uint32_t base = (smem_u32(smem_raw) + 255u) & ~255u;
    const int tid   = threadIdx.x;
    const int node0 = blockIdx.x * 128;

    // ---- fill B: straight uint4 copy of pre-swizzled images ----
    {
        const uint4* gh = (const uint4*)Bhi_g;
        const uint4* gl = (const uint4*)Blo_g;
        #pragma unroll
        for (int i = 0; i < 8; i++) {
            int j = tid + i * 256;
            sts128(base + BHI_OFF + j * 16, __ldg(gh + j));
            sts128(base + BLO_OFF + j * 16, __ldg(gl + j));
        }
    }
    // ---- fill A: fp32 -> bf16 hi/lo, swizzled, STS.128 ----
    {
        int r = tid & 127;
        int half = tid >> 7;
        int m = node0 + r;
        const float* sp;
        float sc = 1.f;
        if (MODE == 0) {
            sp = (half ? Ab : Aa) + (size_t)m * 64;
            if (!half && m < n) sc = __ldg(invd + m);
        } else {
            sp = Aa + (size_t)m * 128 + half * 64;
        }
        #pragma unroll
        for (int g = 0; g < 8; g++) {
            float4 v0 = make_float4(0.f, 0.f, 0.f, 0.f);
            float4 v1 = v0;
            if (m < n) {
                v0 = __ldg((const float4*)(sp + g * 8));
                v1 = __ldg((const float4*)(sp + g * 8 + 4));
            }
            v0.x *= sc; v0.y *= sc; v0.z *= sc; v0.w *= sc;
            v1.x *= sc; v1.y *= sc; v1.z *= sc; v1.w *= sc;
            uint4 hi, lo;
            hi.x = bsplit2(v0.x, v0.y, lo.x);
            hi.y = bsplit2(v0.z, v0.w, lo.y);
            hi.z = bsplit2(v1.x, v1.y, lo.z);
            hi.w = bsplit2(v1.z, v1.w, lo.w);
            uint32_t off = swz(r, (uint32_t)(half * 128 + g * 16));
            sts128(base + AHI_OFF + off, hi);
            sts128(base + ALO_OFF + off, lo);
        }
    }
    __syncthreads();

    // ---- MMA mainloop: warp = m32 x n64 ----
    const int lane = tid & 31, w = tid >> 5;
    const int wm = w & 3;            // m group (32 rows)
    const int wn = w >> 2;           // n half (64 cols)
    float acc[64];                   // [m-tile 0..1][n8-tile 0..7][4]
    #pragma unroll
    for (int i = 0; i < 64; i++) acc[i] = 0.f;

    // A frags: rows wm*32 + t*16 + (lane&15); +16 preserves row&7 -> same xa
    const int ra0 = wm * 32 + (lane & 15);
    const uint32_t a_off0 = base + AHI_OFF + (uint32_t)ra0 * 256u;
    const uint32_t a_off1 = a_off0 + 16u * 256u;
    const uint32_t xa     = ((uint32_t)ra0 & 7u) << 4;
    const uint32_t kca    = ((uint32_t)(lane >> 4)) << 4;
    // B frags: rows wn*64 + p*16 + rb0; rb0&7 == lane&7, +16p preserves row&7
    const int rb0 = (lane & 7) | (((lane >> 4) & 1) << 3);
    const uint32_t b_off = base + BHI_OFF + (uint32_t)(wn * 64 + rb0) * 256u;
    const uint32_t xb    = ((uint32_t)lane & 7u) << 4;
    const uint32_t kcb   = (((uint32_t)lane >> 3) & 1u) << 4;

    for (int ks = 0; ks < 8; ks++) {
        uint32_t a0h[4], a0l[4], a1h[4], a1l[4];
        uint32_t ka = ((uint32_t)(ks * 32) + kca) ^ xa;
        ldsm_x4(a0h, a_off0 + ka);
        ldsm_x4(a0l, a_off0 + (ALO_OFF - AHI_OFF) + ka);
        ldsm_x4(a1h, a_off1 + ka);
        ldsm_x4(a1l, a_off1 + (ALO_OFF - AHI_OFF) + ka);
        uint32_t kb = ((uint32_t)(ks * 32) + kcb) ^ xb;
        #pragma unroll
        for (int p = 0; p < 4; p++) {          // 16 n-rows per iter = 2 n8-tiles
            uint32_t bh[4], bl[4];
            uint32_t baddr = b_off + (uint32_t)p * 4096u + kb;
            ldsm_x4(bh, baddr);
            ldsm_x4(bl, baddr + (BLO_OFF - BHI_OFF));
            float* m0n0 = acc + (0 * 8 + 2 * p) * 4;       // m-tile0, n8-tile 2p
            float* m0n1 = acc + (0 * 8 + 2 * p + 1) * 4;   // m-tile0, n8-tile 2p+1
            float* m1n0 = acc + (1 * 8 + 2 * p) * 4;
            float* m1n1 = acc + (1 * 8 + 2 * p + 1) * 4;
            mma_bf16(m0n0, a0h, bh[0], bh[1]);
            mma_bf16(m0n0, a0l, bh[0], bh[1]);
            mma_bf16(m0n0, a0h, bl[0], bl[1]);
            mma_bf16(m0n1, a0h, bh[2], bh[3]);
            mma_bf16(m0n1, a0l, bh[2], bh[3]);
            mma_bf16(m0n1, a0h, bl[2], bl[3]);
            mma_bf16(m1n0, a1h, bh[0], bh[1]);
            mma_bf16(m1n0, a1l, bh[0], bh[1]);
            mma_bf16(m1n0, a1h, bl[0], bl[1]);
            mma_bf16(m1n1, a1h, bh[2], bh[3]);
            mma_bf16(m1n1, a1l, bh[2], bh[3]);
            mma_bf16(m1n1, a1h, bl[2], bl[3]);
        }
    }

    // ---- epilogue: warp writes m32 x n64 ----
    const int quad = lane >> 2, qt = lane & 3;
    #pragma unroll
    for (int t = 0; t < 2; t++) {
        int r0g = node0 + wm * 32 + t * 16 + quad;
        int r1g = r0g + 8;
        #pragma unroll
        for (int p8 = 0; p8 < 8; p8++) {
            int c = wn * 64 + p8 * 8 + qt * 2;
            int idx = (t * 8 + p8) * 4;
            float2 v0 = make_float2(acc[idx + 0], acc[idx + 1]);
            float2 v1 = make_float2(acc[idx + 2], acc[idx + 3]);
            if (MODE == 0) {
                float2 bb = *(const float2*)(bias + c);
                v0.x = fmaxf(v0.x + bb.x, 0.f); v0.y = fmaxf(v0.y + bb.y, 0.f);
                v1.x = fmaxf(v1.x + bb.x, 0.f); v1.y = fmaxf(v1.y + bb.y, 0.f);
            }
            if (r0g < n) *(float2*)(out + (size_t)r0g * 128 + c) = v0;
            if (r1g < n) *(float2*)(out + (size_t)r1g * 128 + c) = v1;
        }
    }
}

// out[m][c] = sigmoid(agg2[m][c]*invd[m] + S[m][c] + b2[c]),  S = PS[:,64:128]
__global__ void final_kernel(const float* __restrict__ agg2,
                             const float* __restrict__ ps,
                             const float* __restrict__ invd,
                             const float* __restrict__ b2,
                             float* __restrict__ out, int n) {
    int idx = blockIdx.x * blockDim.x + threadIdx.x;
    if (idx >= n * 16) return;
    int m = idx >> 4;
    int q = (idx & 15) * 4;
    float iv = __ldg(&invd[m]);
    float4 a = *(const float4*)(agg2 + (size_t)m * 64 + q);
    float4 s = *(const float4*)(ps + (size_t)m * 128 + 64 + q);
    float4 b = *(const float4*)(b2 + q);
    float4 r;
    r.x = 1.0f / (1.0f + __expf(-(a.x * iv + s.x + b.x)));
    r.y = 1.0f / (1.0f + __expf(-(a.y * iv + s.y + b.y)));
    r.z = 1.0f / (1.0f + __expf(-(a.z * iv + s.z + b.z)));
    r.w = 1.0f / (1.0f + __expf(-(a.w * iv + s.w + b.w)));
    *(float4*)(out + (size_t)m * 64 + q) = r;
}

extern "C" void kernel_launch(void* const* d_in, const int* in_sizes, int n_in,
                              void* d_out, int out_size) {
    const float* x   = (const float*)d_in[0];
    const int*   ei  = (const int*)  d_in[1];
    const float* W1l = (const float*)d_in[2];
    const float* W1r = (const float*)d_in[3];
    const float* b1  = (const float*)d_in[4];
    const float* W2l = (const float*)d_in[5];
    const float* W2r = (const float*)d_in[6];
    const float* b2  = (const float*)d_in[7];
    float* out = (float*)d_out;

    const int n = in_sizes[0] / C_IN;
    const int E = in_sizes[1] / 2;
    const int* src = ei;
    const int* dst = ei + E;

    float *invd, *agg1, *h, *ps, *agg2;
    int *cnt, *startp, *cur, *csrc, *bsum;
    __nv_bfloat16 *b1hi, *b1lo, *b2hi, *b2lo;
    cudaGetSymbolAddress((void**)&invd,  g_invd);
    cudaGetSymbolAddress((void**)&cnt,   g_cnt);
    cudaGetSymbolAddress((void**)&startp,g_start);
    cudaGetSymbolAddress((void**)&cur,   g_cur);
    cudaGetSymbolAddress((void**)&csrc,  g_csrc);
    cudaGetSymbolAddress((void**)&bsum,  g_bsum);
    cudaGetSymbolAddress((void**)&agg1,  g_agg1);
    cudaGetSymbolAddress((void**)&h,     g_h);
    cudaGetSymbolAddress((void**)&ps,    g_ps);
    cudaGetSymbolAddress((void**)&agg2,  g_agg2);
    cudaGetSymbolAddress((void**)&b1hi,  g_b1hi);
    cudaGetSymbolAddress((void**)&b1lo,  g_b1lo);
    cudaGetSymbolAddress((void**)&b2hi,  g_b2hi);
    cudaGetSymbolAddress((void**)&b2lo,  g_b2lo);

    cudaFuncSetAttribute(gemm_mma<0>, cudaFuncAttributeMaxDynamicSharedMemorySize, GEMM_SMEM);
    cudaFuncSetAttribute(gemm_mma<1>, cudaFuncAttributeMaxDynamicSharedMemorySize, GEMM_SMEM);

    cudaMemsetAsync(cnt, 0, (size_t)n * sizeof(int));
    pack_weights<<<64, 256>>>(W1l, W1r, W2l, W2r);

    // ---- CSR build (once, reused by both layers) ----
    const int nb = (n + 1023) / 1024;
    hist_kernel<<<(E + 255) / 256, 256>>>(dst, cnt, E);
    scan_pass1<<<nb, 256>>>(cnt, bsum, n);
    scan_pass2<<<1, 512>>>(bsum, nb);
    scan_pass3<<<nb, 256>>>(cnt, bsum, startp, cur, invd, n);
    permute_kernel<<<(E + 255) / 256, 256>>>(src, dst, cur, csrc, E);

    // ---- layer 1 ----
    agg_csr<<<(n * 16 + 255) / 256, 256>>>(x, C_IN, csrc, startp, cnt, agg1, n);
    const int tiles = (n + 127) / 128;
    gemm_mma<0><<<tiles, 256, GEMM_SMEM>>>(agg1, x, invd, b1hi, b1lo, b1, h, n);

    // ---- layer 2 (dense first via linearity of mean) ----
    gemm_mma<1><<<tiles, 256, GEMM_SMEM>>>(h, nullptr, nullptr, b2hi, b2lo, nullptr, ps, n);
    agg_csr<<<(n * 16 + 255) / 256, 256>>>(ps, C_HID, csrc, startp, cnt, agg2, n);

    // ---- epilogue ----
    final_kernel<<<(n * 16 + 255) / 256, 256>>>(agg2, ps, invd, b2, out, n);
}

// round 15
// speedup vs baseline: 3.8343x; 1.0615x over previous
#include <cuda_runtime.h>
#include <cuda_bf16.h>
#include <cstdint>

#define NODES_MAX 100000
#define EDGES_MAX 1600000
#define C_IN  64
#define C_HID 128

// ---------------- scratch (static __device__, allocation-free) ----------------
__device__ float g_invd[NODES_MAX];                       // 1/max(deg,1)
__device__ int   g_cnt  [NODES_MAX];                      // degree counts
__device__ int   g_start[NODES_MAX];                      // CSR offsets
__device__ int   g_cur  [NODES_MAX];                      // permute cursors
__device__ int   g_csrc [EDGES_MAX];                      // src ids grouped by dst
__device__ int   g_bsum [512];                            // scan block sums
__device__ float g_agg1[(size_t)NODES_MAX * C_IN];
__device__ float g_h   [(size_t)NODES_MAX * C_HID];
__device__ float g_ps  [(size_t)NODES_MAX * C_HID];       // [P | S]
__device__ float g_agg2[(size_t)NODES_MAX * C_IN];
// Weight images: bf16 hi/lo, already in the XOR-swizzled smem layout (straight copy in)
__device__ __align__(16) __nv_bfloat16 g_b1hi[128 * 128];
__device__ __align__(16) __nv_bfloat16 g_b1lo[128 * 128];
__device__ __align__(16) __nv_bfloat16 g_b2hi[128 * 128];
__device__ __align__(16) __nv_bfloat16 g_b2lo[128 * 128];

// ---------------- helpers ----------------
__device__ __forceinline__ uint32_t smem_u32(const void* p) {
    uint32_t a;
    asm("{ .reg .u64 t; cvta.to.shared.u64 t, %1; cvt.u32.u64 %0, t; }" : "=r"(a) : "l"(p));
    return a;
}
__device__ __forceinline__ void sts128(uint32_t addr, uint4 v) {
    asm volatile("st.shared.v4.b32 [%0], {%1,%2,%3,%4};"
                 :: "r"(addr), "r"(v.x), "r"(v.y), "r"(v.z), "r"(v.w));
}
__device__ __forceinline__ void ldsm_x4(uint32_t* r, uint32_t a) {
    asm volatile("ldmatrix.sync.aligned.m8n8.x4.shared.b16 {%0,%1,%2,%3}, [%4];"
                 : "=r"(r[0]), "=r"(r[1]), "=r"(r[2]), "=r"(r[3]) : "r"(a));
}
__device__ __forceinline__ void mma_bf16(float* d, const uint32_t* a, uint32_t b0, uint32_t b1) {
    asm volatile("mma.sync.aligned.m16n8k16.row.col.f32.bf16.bf16.f32 "
                 "{%0,%1,%2,%3}, {%4,%5,%6,%7}, {%8,%9}, {%0,%1,%2,%3};"
                 : "+f"(d[0]), "+f"(d[1]), "+f"(d[2]), "+f"(d[3])
                 : "r"(a[0]), "r"(a[1]), "r"(a[2]), "r"(a[3]), "r"(b0), "r"(b1));
}
__device__ __forceinline__ uint32_t bsplit2(float x, float y, uint32_t& lo) {
    __nv_bfloat16 hx = __float2bfloat16_rn(x);
    __nv_bfloat16 hy = __float2bfloat16_rn(y);
    __nv_bfloat16 lx = __float2bfloat16_rn(x - __bfloat162float(hx));
    __nv_bfloat16 ly = __float2bfloat16_rn(y - __bfloat162float(hy));
    lo = ((uint32_t)__bfloat16_as_ushort(ly) << 16) | (uint32_t)__bfloat16_as_ushort(lx);
    return ((uint32_t)__bfloat16_as_ushort(hy) << 16) | (uint32_t)__bfloat16_as_ushort(hx);
}

// Swizzled byte offset within a [128 rows x 256B] matrix (B images).
__device__ __forceinline__ uint32_t swz(int row, uint32_t kbyte) {
    return (uint32_t)row * 256u + (kbyte ^ (((uint32_t)row & 7u) << 4));
}
// Swizzled byte offset within a [128 rows x 128B] matrix (A chunk).
__device__ __forceinline__ uint32_t swzA(int row, uint32_t kbyte) {
    return (uint32_t)row * 128u + (kbyte ^ (((uint32_t)row & 7u) << 4));
}

// ---------------- weight packing into swizzled bf16 hi/lo images ----------------
__global__ void pack_weights(const float* __restrict__ W1l, const float* __restrict__ W1r,
                             const float* __restrict__ W2l, const float* __restrict__ W2r) {
    int i = blockIdx.x * blockDim.x + threadIdx.x;
    if (i >= 128 * 128) return;
    int nrow = i >> 7, k = i & 127;
    float v1 = (k < 64) ? W1l[nrow * 64 + k] : W1r[nrow * 64 + (k - 64)];
    float v2 = (nrow < 64) ? W2l[nrow * 128 + k] : W2r[(nrow - 64) * 128 + k];
    int e = swz(nrow, (uint32_t)k * 2) >> 1;
    __nv_bfloat16 h1 = __float2bfloat16_rn(v1);
    __nv_bfloat16 h2 = __float2bfloat16_rn(v2);
    g_b1hi[e] = h1; g_b1lo[e] = __float2bfloat16_rn(v1 - __bfloat162float(h1));
    g_b2hi[e] = h2; g_b2lo[e] = __float2bfloat16_rn(v2 - __bfloat162float(h2));
}

// ---------------- CSR build ----------------
__global__ void hist_kernel(const int* __restrict__ dst, int* __restrict__ cnt, int E) {
    int e = blockIdx.x * blockDim.x + threadIdx.x;
    if (e < E) atomicAdd(&cnt[__ldg(&dst[e])], 1);
}

__global__ void scan_pass1(const int* __restrict__ cnt, int* __restrict__ bsum, int n) {
    __shared__ int ws[8];
    int base = blockIdx.x * 1024 + threadIdx.x * 4;
    int s = 0;
    #pragma unroll
    for (int i = 0; i < 4; i++) { int idx = base + i; if (idx < n) s += __ldg(&cnt[idx]); }
    for (int o = 16; o; o >>= 1) s += __shfl_down_sync(~0u, s, o);
    if ((threadIdx.x & 31) == 0) ws[threadIdx.x >> 5] = s;
    __syncthreads();
    if (threadIdx.x < 8) {
        int v = ws[threadIdx.x];
        for (int o = 4; o; o >>= 1) v += __shfl_down_sync(0xff, v, o);
        if (threadIdx.x == 0) bsum[blockIdx.x] = v;
    }
}
__global__ void scan_pass2(int* __restrict__ bsum, int nb) {
    __shared__ int sm[512];
    int t = threadIdx.x;
    int v = (t < nb) ? bsum[t] : 0;
    sm[t] = v;
    __syncthreads();
    for (int o = 1; o < 512; o <<= 1) {
        int u = (t >= o) ? sm[t - o] : 0;
        __syncthreads();
        sm[t] += u;
        __syncthreads();
    }
    if (t < nb) bsum[t] = sm[t] - v;   // exclusive
}
__global__ void scan_pass3(const int* __restrict__ cnt, const int* __restrict__ bsum,
                           int* __restrict__ start, int* __restrict__ cur,
                           float* __restrict__ invd, int n) {
    __shared__ int wsum[8];
    int t = threadIdx.x;
    int base = blockIdx.x * 1024 + t * 4;
    int c[4]; int s = 0;
    #pragma unroll
    for (int i = 0; i < 4; i++) { int idx = base + i; c[i] = (idx < n) ? __ldg(&cnt[idx]) : 0; s += c[i]; }
    int lane = t & 31, w = t >> 5;
    int incl = s;
    for (int o = 1; o < 32; o <<= 1) { int u = __shfl_up_sync(~0u, incl, o); if (lane >= o) incl += u; }
    int excl = incl - s;
    if (lane == 31) wsum[w] = incl;
    __syncthreads();
    if (t < 8) {
        int v = wsum[t], iv = v;
        for (int o = 1; o < 8; o <<= 1) { int u = __shfl_up_sync(0xff, iv, o); if (t >= o) iv += u; }
        wsum[t] = iv - v;
    }
    __syncthreads();
    int off = bsum[blockIdx.x] + wsum[w] + excl;
    #pragma unroll
    for (int i = 0; i < 4; i++) {
        int idx = base + i;
        if (idx < n) {
            start[idx] = off;
            cur[idx]   = off;
            invd[idx]  = 1.0f / fmaxf((float)c[i], 1.0f);
            off += c[i];
        }
    }
}
__global__ void permute_kernel(const int* __restrict__ src, const int* __restrict__ dst,
                               int* __restrict__ cur, int* __restrict__ csrc, int E) {
    int e = blockIdx.x * blockDim.x + threadIdx.x;
    if (e < E) {
        int d = __ldg(&dst[e]);
        int slot = atomicAdd(&cur[d], 1);
        csrc[slot] = __ldg(&src[e]);
    }
}

// ---------------- CSR aggregation (no atomics) ----------------
__global__ void agg_csr(const float* __restrict__ x, int ld,
                        const int* __restrict__ csrc,
                        const int* __restrict__ start,
                        const int* __restrict__ cnt,
                        float* __restrict__ agg, int n) {
    int tid = blockIdx.x * blockDim.x + threadIdx.x;
    int node = tid >> 4;
    if (node >= n) return;
    int q = tid & 15;
    int s0 = __ldg(&start[node]);
    int c  = __ldg(&cnt[node]);
    float4 acc = make_float4(0.f, 0.f, 0.f, 0.f);
    int j = 0;
    for (; j + 4 <= c; j += 4) {
        int sa = __ldg(&csrc[s0 + j]);
        int sb = __ldg(&csrc[s0 + j + 1]);
        int sc = __ldg(&csrc[s0 + j + 2]);
        int sd = __ldg(&csrc[s0 + j + 3]);
        float4 va = __ldg((const float4*)(x + (size_t)sa * ld) + q);
        float4 vb = __ldg((const float4*)(x + (size_t)sb * ld) + q);
        float4 vc = __ldg((const float4*)(x + (size_t)sc * ld) + q);
        float4 vd = __ldg((const float4*)(x + (size_t)sd * ld) + q);
        acc.x += va.x + vb.x + vc.x + vd.x;
        acc.y += va.y + vb.y + vc.y + vd.y;
        acc.z += va.z + vb.z + vc.z + vd.z;
        acc.w += va.w + vb.w + vc.w + vd.w;
    }
    for (; j < c; j++) {
        int s = __ldg(&csrc[s0 + j]);
        float4 v = __ldg((const float4*)(x + (size_t)s * ld) + q);
        acc.x += v.x; acc.y += v.y; acc.z += v.z; acc.w += v.w;
    }
    ((float4*)agg)[(size_t)node * 16 + q] = acc;
}

// ---------------- HMMA bf16 split-precision GEMM: out[Mx128] = A_cat[Mx128] @ B^T ----------
// Occupancy-2 version: B hi/lo resident (64KB), A processed in two 64-K chunks
// through a 32KB hi/lo buffer -> 96KB smem + <=128 regs -> 2 CTAs/SM (was 1).
// Warp tiling m32 x n64 unchanged.
#define A_CH_HI 0
#define A_CH_LO 16384
#define B_HI    32768
#define B_LO    65536
#define GEMM_SMEM (98304 + 256)

template<int MODE>
__global__ __launch_bounds__(256, 2)
void gemm_mma(const float* __restrict__ Aa,
              const float* __restrict__ Ab,
              const float* __restrict__ invd,
              const __nv_bfloat16* __restrict__ Bhi_g,
              const __nv_bfloat16* __restrict__ Blo_g,
              const float* __restrict__ bias,
              float*       __restrict__ out,
              int n) {
    extern __shared__ char smem_raw[];
    const uint32_t base = (smem_u32(smem_raw) + 255u) & ~255u;
    const int tid   = threadIdx.x;
    const int node0 = blockIdx.x * 128;

    // ---- fill B once: straight uint4 copy of pre-swizzled images ----
    {
        const uint4* gh = (const uint4*)Bhi_g;
        const uint4* gl = (const uint4*)Blo_g;
        #pragma unroll
        for (int i = 0; i < 8; i++) {
            int j = tid + i * 256;
            sts128(base + B_HI + j * 16, __ldg(gh + j));
            sts128(base + B_LO + j * 16, __ldg(gl + j));
        }
    }

    const int lane = tid & 31, w = tid >> 5;
    const int wm = w & 3;            // m group (32 rows)
    const int wn = w >> 2;           // n half (64 cols)
    float acc[64];
    #pragma unroll
    for (int i = 0; i < 64; i++) acc[i] = 0.f;

    // A frags (128B rows): rows wm*32 + t*16 + (lane&15)
    const int ra0 = wm * 32 + (lane & 15);
    const uint32_t a_off0 = base + A_CH_HI + (uint32_t)ra0 * 128u;
    const uint32_t a_off1 = a_off0 + 16u * 128u;
    const uint32_t xa     = ((uint32_t)ra0 & 7u) << 4;
    const uint32_t kca    = ((uint32_t)(lane >> 4)) << 4;
    // B frags (256B rows): unchanged
    const int rb0 = (lane & 7) | (((lane >> 4) & 1) << 3);
    const uint32_t b_off = base + B_HI + (uint32_t)(wn * 64 + rb0) * 256u;
    const uint32_t xb    = ((uint32_t)lane & 7u) << 4;
    const uint32_t kcb   = (((uint32_t)lane >> 3) & 1u) << 4;

    // fill-phase thread mapping: row = tid&127, k-half (32k) = tid>>7
    const int fr = tid & 127;
    const int fkh = tid >> 7;
    const int fm = node0 + fr;

    #pragma unroll
    for (int chunk = 0; chunk < 2; chunk++) {
        if (chunk) __syncthreads();   // prior mainloop reads done before refill

        // ---- fill A chunk (128 rows x 64 k, hi/lo bf16, swizzled 128B rows) ----
        {
            const float* sp;
            float sc = 1.f;
            if (MODE == 0) {
                sp = (chunk ? Ab : Aa) + (size_t)fm * 64 + fkh * 32;
                if (!chunk && fm < n) sc = __ldg(invd + fm);
            } else {
                sp = Aa + (size_t)fm * 128 + chunk * 64 + fkh * 32;
            }
            #pragma unroll
            for (int g = 0; g < 4; g++) {
                float4 v0 = make_float4(0.f, 0.f, 0.f, 0.f);
                float4 v1 = v0;
                if (fm < n) {
                    v0 = __ldg((const float4*)(sp + g * 8));
                    v1 = __ldg((const float4*)(sp + g * 8 + 4));
                }
                v0.x *= sc; v0.y *= sc; v0.z *= sc; v0.w *= sc;
                v1.x *= sc; v1.y *= sc; v1.z *= sc; v1.w *= sc;
                uint4 hi, lo;
                hi.x = bsplit2(v0.x, v0.y, lo.x);
                hi.y = bsplit2(v0.z, v0.w, lo.y);
                hi.z = bsplit2(v1.x, v1.y, lo.z);
                hi.w = bsplit2(v1.z, v1.w, lo.w);
                uint32_t off = swzA(fr, (uint32_t)(fkh * 64 + g * 16));
                sts128(base + A_CH_HI + off, hi);
                sts128(base + A_CH_LO + off, lo);
            }
        }
        __syncthreads();

        // ---- 4 K-steps on this chunk ----
        for (int ks = 0; ks < 4; ks++) {
            const int kg = chunk * 4 + ks;    // global K-step for B
            uint32_t a0h[4], a0l[4], a1h[4], a1l[4];
            uint32_t ka = ((uint32_t)(ks * 32) + kca) ^ xa;
            ldsm_x4(a0h, a_off0 + ka);
            ldsm_x4(a0l, a_off0 + (A_CH_LO - A_CH_HI) + ka);
            ldsm_x4(a1h, a_off1 + ka);
            ldsm_x4(a1l, a_off1 + (A_CH_LO - A_CH_HI) + ka);
            uint32_t kb = ((uint32_t)(kg * 32) + kcb) ^ xb;
            #pragma unroll
            for (int p = 0; p < 4; p++) {
                uint32_t bh[4], bl[4];
                uint32_t baddr = b_off + (uint32_t)p * 4096u + kb;
                ldsm_x4(bh, baddr);
                ldsm_x4(bl, baddr + (B_LO - B_HI));
                float* m0n0 = acc + (0 * 8 + 2 * p) * 4;
                float* m0n1 = acc + (0 * 8 + 2 * p + 1) * 4;
                float* m1n0 = acc + (1 * 8 + 2 * p) * 4;
                float* m1n1 = acc + (1 * 8 + 2 * p + 1) * 4;
                mma_bf16(m0n0, a0h, bh[0], bh[1]);
                mma_bf16(m0n0, a0l, bh[0], bh[1]);
                mma_bf16(m0n0, a0h, bl[0], bl[1]);
                mma_bf16(m0n1, a0h, bh[2], bh[3]);
                mma_bf16(m0n1, a0l, bh[2], bh[3]);
                mma_bf16(m0n1, a0h, bl[2], bl[3]);
                mma_bf16(m1n0, a1h, bh[0], bh[1]);
                mma_bf16(m1n0, a1l, bh[0], bh[1]);
                mma_bf16(m1n0, a1h, bl[0], bl[1]);
                mma_bf16(m1n1, a1h, bh[2], bh[3]);
                mma_bf16(m1n1, a1l, bh[2], bh[3]);
                mma_bf16(m1n1, a1h, bl[2], bl[3]);
            }
        }
    }

    // ---- epilogue: warp writes m32 x n64 ----
    const int quad = lane >> 2, qt = lane & 3;
    #pragma unroll
    for (int t = 0; t < 2; t++) {
        int r0g = node0 + wm * 32 + t * 16 + quad;
        int r1g = r0g + 8;
        #pragma unroll
        for (int p8 = 0; p8 < 8; p8++) {
            int c = wn * 64 + p8 * 8 + qt * 2;
            int idx = (t * 8 + p8) * 4;
            float2 v0 = make_float2(acc[idx + 0], acc[idx + 1]);
            float2 v1 = make_float2(acc[idx + 2], acc[idx + 3]);
            if (MODE == 0) {
                float2 bb = *(const float2*)(bias + c);
                v0.x = fmaxf(v0.x + bb.x, 0.f); v0.y = fmaxf(v0.y + bb.y, 0.f);
                v1.x = fmaxf(v1.x + bb.x, 0.f); v1.y = fmaxf(v1.y + bb.y, 0.f);
            }
            if (r0g < n) *(float2*)(out + (size_t)r0g * 128 + c) = v0;
            if (r1g < n) *(float2*)(out + (size_t)r1g * 128 + c) = v1;
        }
    }
}

// out[m][c] = sigmoid(agg2[m][c]*invd[m] + S[m][c] + b2[c]),  S = PS[:,64:128]
__global__ void final_kernel(const float* __restrict__ agg2,
                             const float* __restrict__ ps,
                             const float* __restrict__ invd,
                             const float* __restrict__ b2,
                             float* __restrict__ out, int n) {
    int idx = blockIdx.x * blockDim.x + threadIdx.x;
    if (idx >= n * 16) return;
    int m = idx >> 4;
    int q = (idx & 15) * 4;
    float iv = __ldg(&invd[m]);
    float4 a = *(const float4*)(agg2 + (size_t)m * 64 + q);
    float4 s = *(const float4*)(ps + (size_t)m * 128 + 64 + q);
    float4 b = *(const float4*)(b2 + q);
    float4 r;
    r.x = 1.0f / (1.0f + __expf(-(a.x * iv + s.x + b.x)));
    r.y = 1.0f / (1.0f + __expf(-(a.y * iv + s.y + b.y)));
    r.z = 1.0f / (1.0f + __expf(-(a.z * iv + s.z + b.z)));
    r.w = 1.0f / (1.0f + __expf(-(a.w * iv + s.w + b.w)));
    *(float4*)(out + (size_t)m * 64 + q) = r;
}

extern "C" void kernel_launch(void* const* d_in, const int* in_sizes, int n_in,
                              void* d_out, int out_size) {
    const float* x   = (const float*)d_in[0];
    const int*   ei  = (const int*)  d_in[1];
    const float* W1l = (const float*)d_in[2];
    const float* W1r = (const float*)d_in[3];
    const float* b1  = (const float*)d_in[4];
    const float* W2l = (const float*)d_in[5];
    const float* W2r = (const float*)d_in[6];
    const float* b2  = (const float*)d_in[7];
    float* out = (float*)d_out;

    const int n = in_sizes[0] / C_IN;
    const int E = in_sizes[1] / 2;
    const int* src = ei;
    const int* dst = ei + E;

    float *invd, *agg1, *h, *ps, *agg2;
    int *cnt, *startp, *cur, *csrc, *bsum;
    __nv_bfloat16 *b1hi, *b1lo, *b2hi, *b2lo;
    cudaGetSymbolAddress((void**)&invd,  g_invd);
    cudaGetSymbolAddress((void**)&cnt,   g_cnt);
    cudaGetSymbolAddress((void**)&startp,g_start);
    cudaGetSymbolAddress((void**)&cur,   g_cur);
    cudaGetSymbolAddress((void**)&csrc,  g_csrc);
    cudaGetSymbolAddress((void**)&bsum,  g_bsum);
    cudaGetSymbolAddress((void**)&agg1,  g_agg1);
    cudaGetSymbolAddress((void**)&h,     g_h);
    cudaGetSymbolAddress((void**)&ps,    g_ps);
    cudaGetSymbolAddress((void**)&agg2,  g_agg2);
    cudaGetSymbolAddress((void**)&b1hi,  g_b1hi);
    cudaGetSymbolAddress((void**)&b1lo,  g_b1lo);
    cudaGetSymbolAddress((void**)&b2hi,  g_b2hi);
    cudaGetSymbolAddress((void**)&b2lo,  g_b2lo);

    cudaFuncSetAttribute(gemm_mma<0>, cudaFuncAttributeMaxDynamicSharedMemorySize, GEMM_SMEM);
    cudaFuncSetAttribute(gemm_mma<1>, cudaFuncAttributeMaxDynamicSharedMemorySize, GEMM_SMEM);

    cudaMemsetAsync(cnt, 0, (size_t)n * sizeof(int));
    pack_weights<<<64, 256>>>(W1l, W1r, W2l, W2r);

    // ---- CSR build (once, reused by both layers) ----
    const int nb = (n + 1023) / 1024;
    hist_kernel<<<(E + 255) / 256, 256>>>(dst, cnt, E);
    scan_pass1<<<nb, 256>>>(cnt, bsum, n);
    scan_pass2<<<1, 512>>>(bsum, nb);
    scan_pass3<<<nb, 256>>>(cnt, bsum, startp, cur, invd, n);
    permute_kernel<<<(E + 255) / 256, 256>>>(src, dst, cur, csrc, E);

    // ---- layer 1 ----
    agg_csr<<<(n * 16 + 255) / 256, 256>>>(x, C_IN, csrc, startp, cnt, agg1, n);
    const int tiles = (n + 127) / 128;
    gemm_mma<0><<<tiles, 256, GEMM_SMEM>>>(agg1, x, invd, b1hi, b1lo, b1, h, n);

    // ---- layer 2 (dense first via linearity of mean) ----
    gemm_mma<1><<<tiles, 256, GEMM_SMEM>>>(h, nullptr, nullptr, b2hi, b2lo, nullptr, ps, n);
    agg_csr<<<(n * 16 + 255) / 256, 256>>>(ps, C_HID, csrc, startp, cnt, agg2, n);

    // ---- epilogue ----
    final_kernel<<<(n * 16 + 255) / 256, 256>>>(agg2, ps, invd, b2, out, n);
}